// round 9
// baseline (speedup 1.0000x reference)
#include <cuda_runtime.h>
#include <cuda_fp16.h>
#include <math.h>

#define MAXN 100000
#define MAXE 1600000
#define MAXG 128
#define MAXB 1024

// ---------------- scratch (static __device__ — zero-initialized at load) ----------------
__device__ int   g_deg[MAXN];          // zeroed by finalize of previous replay (and at load)
__device__ float g_dinv[MAXN];
__device__ int   g_rowptr[MAXN + 1];
__device__ int   g_cursor[MAXN];
__device__ int   g_col[MAXE];
__device__ float g_ew[MAXE];
__device__ int   g_bsums[MAXB];
__device__ float g_B1[(size_t)MAXN * 64];
__device__ float g_B2[(size_t)MAXN * 64];
__device__ float g_B3[(size_t)MAXN * 64];
__device__ float g_B4[(size_t)MAXN * 64];
__device__ __half g_F1[(size_t)MAXN * 64];   // fp16 gather operands (64-dim)
__device__ __half g_F2[(size_t)MAXN * 64];
__device__ __half g_feat16[(size_t)MAXN * 16];
__device__ __half g_x116[(size_t)MAXN * 16];
__device__ float g_gsum[MAXG * 64];
__device__ int   g_gcnt[MAXG];
__device__ unsigned g_epoch;   // monotonically increasing across replays
__device__ unsigned g_cnt;

// ---------------- packed f32x2 helpers (FFMA2 — PTX-only on sm_103a) ----------------
__device__ __forceinline__ void ffma2(unsigned long long& acc, unsigned long long w,
                                      unsigned long long x) {
    asm("fma.rn.f32x2 %0, %1, %2, %3;" : "=l"(acc) : "l"(w), "l"(x), "l"(acc));
}
__device__ __forceinline__ unsigned long long pack2(float a, float b) {
    unsigned long long r;
    asm("mov.b64 %0, {%1, %2};" : "=l"(r) : "f"(a), "f"(b));
    return r;
}
__device__ __forceinline__ float2 unpack2(unsigned long long r) {
    float2 f;
    asm("mov.b64 {%0, %1}, %2;" : "=f"(f.x), "=f"(f.y) : "l"(r));
    return f;
}

// ---------------- half2 <-> float2 helpers ----------------
__device__ __forceinline__ float2 h2f(unsigned u) {
    __half2 h = *reinterpret_cast<__half2*>(&u);
    return __half22float2(h);
}
__device__ __forceinline__ unsigned f2h(float a, float b) {
    __half2 h = __floats2half2_rn(a, b);
    return *reinterpret_cast<unsigned*>(&h);
}

// ---------------- grid-wide barrier (all blocks co-resident by construction) ----------------
__device__ __forceinline__ void gsync(int nb) {
    __syncthreads();
    if (threadIdx.x == 0) {
        __threadfence();                       // release
        volatile unsigned* ep = &g_epoch;
        unsigned e = *ep;
        if (atomicAdd(&g_cnt, 1u) == (unsigned)(nb - 1)) {
            g_cnt = 0;
            __threadfence();
            *ep = e + 1;
        } else {
            while (*ep == e) {}
            __threadfence();                   // acquire
        }
    }
    __syncthreads();
}

// ---------------- phase helpers ----------------
// out = alpha * dinv_i * sum_e w_e * f16[col_e]  (+ beta * extra_i), 64-dim fp16 gather
__device__ void ph_aggr64h(const __half* __restrict__ f16, const float* __restrict__ extra,
                           float* __restrict__ out, __half* __restrict__ out16,
                           float alpha, float beta, int n, int gw, int nwarps) {
    const int lane = threadIdx.x & 31;
    const int sub = lane >> 4;
    const int c = (lane & 15) * 4;
    for (int node = gw; node < n; node += nwarps) {
        const int beg = g_rowptr[node], end = g_rowptr[node + 1];
        float4 acc = make_float4(0.f, 0.f, 0.f, 0.f);
        for (int e = beg; e < end; e += 8) {
            int ea = e + sub, eb = e + 2 + sub, ec = e + 4 + sub, ed = e + 6 + sub;
            bool va = ea < end, vb = eb < end, vc = ec < end, vd = ed < end;
            int   sa = va ? g_col[ea] : 0;  float wa = va ? g_ew[ea] : 0.f;
            int   sb = vb ? g_col[eb] : 0;  float wb = vb ? g_ew[eb] : 0.f;
            int   sc = vc ? g_col[ec] : 0;  float wc = vc ? g_ew[ec] : 0.f;
            int   sd = vd ? g_col[ed] : 0;  float wd = vd ? g_ew[ed] : 0.f;
            uint2 ra = *(const uint2*)(f16 + (size_t)sa * 64 + c);
            uint2 rb = *(const uint2*)(f16 + (size_t)sb * 64 + c);
            uint2 rc = *(const uint2*)(f16 + (size_t)sc * 64 + c);
            uint2 rd = *(const uint2*)(f16 + (size_t)sd * 64 + c);
            float2 a0 = h2f(ra.x), a1 = h2f(ra.y);
            float2 b0 = h2f(rb.x), b1 = h2f(rb.y);
            float2 c0 = h2f(rc.x), c1 = h2f(rc.y);
            float2 d0 = h2f(rd.x), d1 = h2f(rd.y);
            acc.x = fmaf(wa, a0.x, acc.x); acc.y = fmaf(wa, a0.y, acc.y);
            acc.z = fmaf(wa, a1.x, acc.z); acc.w = fmaf(wa, a1.y, acc.w);
            acc.x = fmaf(wb, b0.x, acc.x); acc.y = fmaf(wb, b0.y, acc.y);
            acc.z = fmaf(wb, b1.x, acc.z); acc.w = fmaf(wb, b1.y, acc.w);
            acc.x = fmaf(wc, c0.x, acc.x); acc.y = fmaf(wc, c0.y, acc.y);
            acc.z = fmaf(wc, c1.x, acc.z); acc.w = fmaf(wc, c1.y, acc.w);
            acc.x = fmaf(wd, d0.x, acc.x); acc.y = fmaf(wd, d0.y, acc.y);
            acc.z = fmaf(wd, d1.x, acc.z); acc.w = fmaf(wd, d1.y, acc.w);
        }
        acc.x += __shfl_xor_sync(0xFFFFFFFFu, acc.x, 16);
        acc.y += __shfl_xor_sync(0xFFFFFFFFu, acc.y, 16);
        acc.z += __shfl_xor_sync(0xFFFFFFFFu, acc.z, 16);
        acc.w += __shfl_xor_sync(0xFFFFFFFFu, acc.w, 16);
        if (sub == 0) {
            float s = alpha * g_dinv[node];
            float4 r = make_float4(s * acc.x, s * acc.y, s * acc.z, s * acc.w);
            if (extra) {
                float4 ex = *(const float4*)(extra + (size_t)node * 64 + c);
                r.x = fmaf(beta, ex.x, r.x); r.y = fmaf(beta, ex.y, r.y);
                r.z = fmaf(beta, ex.z, r.z); r.w = fmaf(beta, ex.w, r.w);
            }
            *(float4*)(out + (size_t)node * 64 + c) = r;
            if (out16)
                *(uint2*)(out16 + (size_t)node * 64 + c) =
                    make_uint2(f2h(r.x, r.y), f2h(r.z, r.w));
        }
    }
}

// 16-dim variant, fp16 gather
__device__ void ph_aggr16h(const __half* __restrict__ f16, const float* __restrict__ extra,
                           float* __restrict__ out, __half* __restrict__ out16,
                           float alpha, float beta, int n, int gw, int nwarps) {
    const int lane = threadIdx.x & 31;
    const int sub = lane >> 2;
    const int c = (lane & 3) * 4;
    for (int node = gw; node < n; node += nwarps) {
        const int beg = g_rowptr[node], end = g_rowptr[node + 1];
        float4 acc = make_float4(0.f, 0.f, 0.f, 0.f);
        for (int e = beg; e < end; e += 16) {
            int e0 = e + sub, e1 = e + 8 + sub;
            bool v0 = e0 < end, v1 = e1 < end;
            int   s0 = v0 ? g_col[e0] : 0;  float w0 = v0 ? g_ew[e0] : 0.f;
            int   s1 = v1 ? g_col[e1] : 0;  float w1 = v1 ? g_ew[e1] : 0.f;
            uint2 r0 = *(const uint2*)(f16 + (size_t)s0 * 16 + c);
            uint2 r1 = *(const uint2*)(f16 + (size_t)s1 * 16 + c);
            float2 a0 = h2f(r0.x), a1 = h2f(r0.y);
            float2 b0 = h2f(r1.x), b1 = h2f(r1.y);
            acc.x = fmaf(w0, a0.x, acc.x); acc.y = fmaf(w0, a0.y, acc.y);
            acc.z = fmaf(w0, a1.x, acc.z); acc.w = fmaf(w0, a1.y, acc.w);
            acc.x = fmaf(w1, b0.x, acc.x); acc.y = fmaf(w1, b0.y, acc.y);
            acc.z = fmaf(w1, b1.x, acc.z); acc.w = fmaf(w1, b1.y, acc.w);
        }
#pragma unroll
        for (int o = 4; o < 32; o <<= 1) {
            acc.x += __shfl_xor_sync(0xFFFFFFFFu, acc.x, o);
            acc.y += __shfl_xor_sync(0xFFFFFFFFu, acc.y, o);
            acc.z += __shfl_xor_sync(0xFFFFFFFFu, acc.z, o);
            acc.w += __shfl_xor_sync(0xFFFFFFFFu, acc.w, o);
        }
        if (lane < 4) {
            float s = alpha * g_dinv[node];
            float4 r = make_float4(s * acc.x, s * acc.y, s * acc.z, s * acc.w);
            if (extra) {
                float4 ex = *(const float4*)(extra + (size_t)node * 16 + c);
                r.x = fmaf(beta, ex.x, r.x); r.y = fmaf(beta, ex.y, r.y);
                r.z = fmaf(beta, ex.z, r.z); r.w = fmaf(beta, ex.w, r.w);
            }
            *(float4*)(out + (size_t)node * 16 + c) = r;
            if (out16)
                *(uint2*)(out16 + (size_t)node * 16 + c) =
                    make_uint2(f2h(r.x, r.y), f2h(r.z, r.w));
        }
    }
}

// out_i = relu(U_i - min_{j->i} V_j), V gathered as fp16; writes fp32 + fp16 copies
__device__ void ph_edge_minh(const float* __restrict__ U, const __half* __restrict__ V16,
                             float* __restrict__ out, __half* __restrict__ out16,
                             int n, int gw, int nwarps) {
    const int lane = threadIdx.x & 31;
    const int sub = lane >> 4;
    const int c = (lane & 15) * 4;
    const float INF = 3.4e38f;
    for (int node = gw; node < n; node += nwarps) {
        const int beg = g_rowptr[node], end = g_rowptr[node + 1];
        float4 mn = make_float4(INF, INF, INF, INF);
        for (int e = beg; e < end; e += 8) {
            int ea = e + sub, eb = e + 2 + sub, ec = e + 4 + sub, ed = e + 6 + sub;
            bool va = ea < end, vb = eb < end, vc = ec < end, vd = ed < end;
            int sa = va ? g_col[ea] : 0;
            int sb = vb ? g_col[eb] : 0;
            int sc = vc ? g_col[ec] : 0;
            int sd = vd ? g_col[ed] : 0;
            uint2 ra = *(const uint2*)(V16 + (size_t)sa * 64 + c);
            uint2 rb = *(const uint2*)(V16 + (size_t)sb * 64 + c);
            uint2 rc = *(const uint2*)(V16 + (size_t)sc * 64 + c);
            uint2 rd = *(const uint2*)(V16 + (size_t)sd * 64 + c);
            float2 a0 = h2f(ra.x), a1 = h2f(ra.y);
            float2 b0 = h2f(rb.x), b1 = h2f(rb.y);
            float2 c0 = h2f(rc.x), c1 = h2f(rc.y);
            float2 d0 = h2f(rd.x), d1 = h2f(rd.y);
            if (va) { mn.x = fminf(mn.x, a0.x); mn.y = fminf(mn.y, a0.y);
                      mn.z = fminf(mn.z, a1.x); mn.w = fminf(mn.w, a1.y); }
            if (vb) { mn.x = fminf(mn.x, b0.x); mn.y = fminf(mn.y, b0.y);
                      mn.z = fminf(mn.z, b1.x); mn.w = fminf(mn.w, b1.y); }
            if (vc) { mn.x = fminf(mn.x, c0.x); mn.y = fminf(mn.y, c0.y);
                      mn.z = fminf(mn.z, c1.x); mn.w = fminf(mn.w, c1.y); }
            if (vd) { mn.x = fminf(mn.x, d0.x); mn.y = fminf(mn.y, d0.y);
                      mn.z = fminf(mn.z, d1.x); mn.w = fminf(mn.w, d1.y); }
        }
        mn.x = fminf(mn.x, __shfl_xor_sync(0xFFFFFFFFu, mn.x, 16));
        mn.y = fminf(mn.y, __shfl_xor_sync(0xFFFFFFFFu, mn.y, 16));
        mn.z = fminf(mn.z, __shfl_xor_sync(0xFFFFFFFFu, mn.z, 16));
        mn.w = fminf(mn.w, __shfl_xor_sync(0xFFFFFFFFu, mn.w, 16));
        if (sub == 0) {
            float4 r = make_float4(0.f, 0.f, 0.f, 0.f);
            if (end > beg) {
                float4 u = *(const float4*)(U + (size_t)node * 64 + c);
                r.x = fmaxf(u.x - mn.x, 0.f); r.y = fmaxf(u.y - mn.y, 0.f);
                r.z = fmaxf(u.z - mn.z, 0.f); r.w = fmaxf(u.w - mn.w, 0.f);
            }
            *(float4*)(out + (size_t)node * 64 + c) = r;
            *(uint2*)(out16 + (size_t)node * 64 + c) =
                make_uint2(f2h(r.x, r.y), f2h(r.z, r.w));
        }
    }
}

// packed-FMA inner sweep: acc[0..7] (f32x2 pairs) += Ws[k][cbase..cbase+15] * x
__device__ __forceinline__ void gemm_sweep_k(unsigned long long* acc, const float (*Ws)[64],
                                             const float* xcol, int D, int cbase) {
    for (int k = 0; k < D; k++) {
        unsigned long long xx = pack2(xcol[k], xcol[k]);
        const ulonglong2* wrow = (const ulonglong2*)&Ws[k][cbase];
        ulonglong2 wA = wrow[0], wB = wrow[1], wC = wrow[2], wD = wrow[3];
        ffma2(acc[0], wA.x, xx); ffma2(acc[1], wA.y, xx);
        ffma2(acc[2], wB.x, xx); ffma2(acc[3], wB.y, xx);
        ffma2(acc[4], wC.x, xx); ffma2(acc[5], wC.y, xx);
        ffma2(acc[6], wD.x, xx); ffma2(acc[7], wD.y, xx);
    }
}

// Fused: H = relu(sum_j Xj@W[j] + bias) (smem only); U = H@(Wt+Wp)+bt+bp (fp32); V16 = H@Wt (fp16)
template <int D>
__device__ void ph_fused_gemm(const float* __restrict__ X0, const float* __restrict__ X1,
                              const float* __restrict__ X2, const float* __restrict__ W,
                              const float* __restrict__ bias,
                              const float* __restrict__ Wt, const float* __restrict__ Wp,
                              const float* __restrict__ bt, const float* __restrict__ bp,
                              float* __restrict__ U, __half* __restrict__ V16, int n,
                              float (*XH)[68], float (*Ws)[64]) {
    const int tid = threadIdx.x;
    const int m = tid >> 2;
    const int cbase = (tid & 3) * 16;
    const int ntiles = (n + 63) >> 6;
    for (int t = blockIdx.x; t < ntiles; t += gridDim.x) {
        const int node0 = t * 64;
        const int node = node0 + m;
        unsigned long long acc[8];
#pragma unroll
        for (int p = 0; p < 8; p++) acc[p] = pack2(__ldg(&bias[cbase + 2 * p]),
                                                   __ldg(&bias[cbase + 2 * p + 1]));
        const float* Xsrc[3] = {X0, X1, X2};
#pragma unroll
        for (int j = 0; j < 3; j++) {
            __syncthreads();
            const float* Xj = Xsrc[j];
            for (int i = tid; i < 64 * D; i += 256) {
                int r = i / D, c2 = i - r * D;
                int nn = node0 + r;
                XH[r][c2] = (nn < n) ? Xj[(size_t)nn * D + c2] : 0.f;
            }
            for (int i = tid; i < D * 64; i += 256) Ws[i >> 6][i & 63] = W[j * D * 64 + i];
            __syncthreads();
            gemm_sweep_k(acc, (const float (*)[64])Ws, &XH[m][0], D, cbase);
        }
        __syncthreads();
        // relu -> H tile in smem
#pragma unroll
        for (int p = 0; p < 8; p += 2) {
            float2 a = unpack2(acc[p]), b2 = unpack2(acc[p + 1]);
            float4 h;
            h.x = fmaxf(a.x, 0.f); h.y = fmaxf(a.y, 0.f);
            h.z = fmaxf(b2.x, 0.f); h.w = fmaxf(b2.y, 0.f);
            *(float4*)&XH[m][cbase + p * 2] = h;
        }
        for (int i = tid; i < 4096; i += 256) Ws[i >> 6][i & 63] = Wt[i] + Wp[i];
        __syncthreads();
#pragma unroll
        for (int p = 0; p < 8; p++)
            acc[p] = pack2(__ldg(&bt[cbase + 2 * p]) + __ldg(&bp[cbase + 2 * p]),
                           __ldg(&bt[cbase + 2 * p + 1]) + __ldg(&bp[cbase + 2 * p + 1]));
        gemm_sweep_k(acc, (const float (*)[64])Ws, &XH[m][0], 64, cbase);
        if (node < n) {
#pragma unroll
            for (int p = 0; p < 8; p += 2) {
                float2 a = unpack2(acc[p]), b2 = unpack2(acc[p + 1]);
                *(float4*)&U[(size_t)node * 64 + cbase + p * 2] = make_float4(a.x, a.y, b2.x, b2.y);
            }
        }
        __syncthreads();
        for (int i = tid; i < 4096; i += 256) Ws[i >> 6][i & 63] = Wt[i];
        __syncthreads();
#pragma unroll
        for (int p = 0; p < 8; p++) acc[p] = 0ull;   // two packed 0.0f
        gemm_sweep_k(acc, (const float (*)[64])Ws, &XH[m][0], 64, cbase);
        if (node < n) {
#pragma unroll
            for (int p = 0; p < 8; p += 2) {
                float2 a = unpack2(acc[p]), b2 = unpack2(acc[p + 1]);
                *(uint2*)&V16[(size_t)node * 64 + cbase + p * 2] =
                    make_uint2(f2h(a.x, a.y), f2h(b2.x, b2.y));
            }
        }
        __syncthreads();
    }
}

// Final Cheb layer: out = relu(X0@W0 + X1@W1 + X2@W2 + bias)
__device__ void ph_cheb_gemm(const float* __restrict__ X0, const float* __restrict__ X1,
                             const float* __restrict__ X2, const float* __restrict__ W,
                             const float* __restrict__ bias, float* __restrict__ out, int n,
                             float (*Xs)[68], float (*Ws)[64]) {
    const int tid = threadIdx.x;
    const int m = tid >> 2;
    const int cbase = (tid & 3) * 16;
    const int ntiles = (n + 63) >> 6;
    for (int t = blockIdx.x; t < ntiles; t += gridDim.x) {
        const int node0 = t * 64;
        const int node = node0 + m;
        unsigned long long acc[8];
#pragma unroll
        for (int p = 0; p < 8; p++) acc[p] = pack2(__ldg(&bias[cbase + 2 * p]),
                                                   __ldg(&bias[cbase + 2 * p + 1]));
        const float* Xsrc[3] = {X0, X1, X2};
#pragma unroll
        for (int j = 0; j < 3; j++) {
            __syncthreads();
            const float* Xj = Xsrc[j];
            for (int i = tid; i < 4096; i += 256) {
                int r = i >> 6, c2 = i & 63;
                int nn = node0 + r;
                Xs[r][c2] = (nn < n) ? Xj[(size_t)nn * 64 + c2] : 0.f;
                Ws[r][c2] = W[j * 4096 + i];
            }
            __syncthreads();
            gemm_sweep_k(acc, (const float (*)[64])Ws, &Xs[m][0], 64, cbase);
        }
        if (node < n) {
#pragma unroll
            for (int p = 0; p < 8; p += 2) {
                float2 a = unpack2(acc[p]), b2 = unpack2(acc[p + 1]);
                float4 r;
                r.x = fmaxf(a.x, 0.f); r.y = fmaxf(a.y, 0.f);
                r.z = fmaxf(b2.x, 0.f); r.w = fmaxf(b2.y, 0.f);
                *(float4*)&out[(size_t)node * 64 + cbase + p * 2] = r;
            }
        }
        __syncthreads();
    }
}

// ---------------- the single persistent kernel ----------------
__global__ void __launch_bounds__(256, 4) mega_kernel(
    const float* __restrict__ feat, const int* __restrict__ src,
    const int* __restrict__ dst, const int* __restrict__ gid,
    const float* __restrict__ W1, const float* __restrict__ b1,
    const float* __restrict__ W2, const float* __restrict__ b2,
    const float* __restrict__ W3, const float* __restrict__ b3,
    const float* __restrict__ Wt1, const float* __restrict__ bt1,
    const float* __restrict__ Wp1, const float* __restrict__ bp1,
    const float* __restrict__ Wt2, const float* __restrict__ bt2,
    const float* __restrict__ Wp2, const float* __restrict__ bp2,
    float* __restrict__ out, int n, int e, int G) {
    __shared__ __align__(16) float sA[64][68];
    __shared__ __align__(16) float sB[64][64];
    __shared__ int s_ws[9];
    __shared__ int s_run;

    const int nb = gridDim.x;
    const int tid = threadIdx.x;
    const int lane = tid & 31, wid = tid >> 5;
    const int gtid = blockIdx.x * 256 + tid;
    const int nthreads = nb * 256;
    const int gw = blockIdx.x * 8 + wid;      // global warp id
    const int nwarps = nb * 8;

    // ---- B: degree count + fp16 copy of input features ----
    for (int i = gtid; i < e; i += nthreads) atomicAdd(&g_deg[dst[i]], 1);
    for (int i = gtid; i < n * 16; i += nthreads) g_feat16[i] = __float2half(feat[i]);
    gsync(nb);

    // ---- C1: per-block exclusive scan of g_deg chunk; zero pooling accumulators ----
    for (int i = gtid; i < G * 64; i += nthreads) g_gsum[i] = 0.f;
    for (int i = gtid; i < G; i += nthreads) g_gcnt[i] = 0;
    const int per = (n + nb - 1) / nb;
    const int rng0 = blockIdx.x * per;
    const int rng1 = min(n, rng0 + per);
    if (tid == 0) s_run = 0;
    __syncthreads();
    for (int t0 = rng0; t0 < rng1; t0 += 1024) {
        int base = t0 + tid * 4;
        int v[4]; int s = 0;
#pragma unroll
        for (int j = 0; j < 4; j++) { int i = base + j; v[j] = (i < rng1) ? g_deg[i] : 0; s += v[j]; }
        int inc = s;
#pragma unroll
        for (int o = 1; o < 32; o <<= 1) { int x = __shfl_up_sync(0xFFFFFFFFu, inc, o); if (lane >= o) inc += x; }
        if (lane == 31) s_ws[wid] = inc;
        __syncthreads();
        if (wid == 0) {
            int w = (lane < 8) ? s_ws[lane] : 0;
            int winc = w;
#pragma unroll
            for (int o = 1; o < 8; o <<= 1) { int x = __shfl_up_sync(0xFFFFFFFFu, winc, o); if (lane >= o) winc += x; }
            if (lane < 8) s_ws[lane] = winc - w;
            if (lane == 7) s_ws[8] = winc;
        }
        __syncthreads();
        int off = s_run + s_ws[wid] + (inc - s);
#pragma unroll
        for (int j = 0; j < 4; j++) { int i = base + j; if (i < rng1) { g_rowptr[i] = off; off += v[j]; } }
        __syncthreads();
        if (tid == 0) s_run += s_ws[8];
        __syncthreads();
    }
    if (tid == 0) g_bsums[blockIdx.x] = s_run;
    gsync(nb);

    // ---- C3: block 0 scans block totals (nb <= 1024) ----
    if (blockIdx.x == 0) {
        int base = tid * 4;
        int v[4]; int s = 0;
#pragma unroll
        for (int j = 0; j < 4; j++) { int i = base + j; v[j] = (i < nb) ? g_bsums[i] : 0; s += v[j]; }
        int inc = s;
#pragma unroll
        for (int o = 1; o < 32; o <<= 1) { int x = __shfl_up_sync(0xFFFFFFFFu, inc, o); if (lane >= o) inc += x; }
        if (lane == 31) s_ws[wid] = inc;
        __syncthreads();
        if (wid == 0) {
            int w = (lane < 8) ? s_ws[lane] : 0;
            int winc = w;
#pragma unroll
            for (int o = 1; o < 8; o <<= 1) { int x = __shfl_up_sync(0xFFFFFFFFu, winc, o); if (lane >= o) winc += x; }
            if (lane < 8) s_ws[lane] = winc - w;
        }
        __syncthreads();
        int off = s_ws[wid] + (inc - s);
#pragma unroll
        for (int j = 0; j < 4; j++) { int i = base + j; if (i < nb) { g_bsums[i] = off; off += v[j]; } }
    }
    gsync(nb);

    // ---- C5: add block offsets; cursor; dinv; rowptr[n] ----
    {
        int off = g_bsums[blockIdx.x];
        for (int i = rng0 + tid; i < rng1; i += 256) {
            int r = g_rowptr[i] + off;
            g_rowptr[i] = r;
            g_cursor[i] = r;
            int d = g_deg[i];
            g_dinv[i] = (d > 0) ? rsqrtf((float)d) : 1.0f;
        }
        if (gtid == 0) g_rowptr[n] = e;
    }
    gsync(nb);

    // ---- D: fill CSR ----
    for (int i = gtid; i < e; i += nthreads) {
        int d = dst[i], s = src[i];
        int p = atomicAdd(&g_cursor[d], 1);
        g_col[p] = s;
        g_ew[p] = g_dinv[s];
    }
    gsync(nb);

    // ---- Layer 1 (Cheb 16->64): X1 = -aggr(feat), X2 = -2*aggr(X1) - feat ----
    ph_aggr16h(g_feat16, nullptr, g_B1, g_x116, -1.f, 0.f, n, gw, nwarps);
    gsync(nb);
    ph_aggr16h(g_x116, feat, g_B2, nullptr, -2.f, -1.f, n, gw, nwarps);
    gsync(nb);
    // ---- Layers 1+2 GEMMs: H1 (smem) -> U=B3 (fp32), V=F1 (fp16) ----
    ph_fused_gemm<16>(feat, g_B1, g_B2, W1, b1, Wt1, Wp1, bt1, bp1, g_B3, g_F1, n, sA, sB);
    gsync(nb);
    ph_edge_minh(g_B3, g_F1, g_B1, g_F2, n, gw, nwarps);     // H2 -> B1 + F2
    gsync(nb);

    // ---- Layer 3 (Cheb 64->64) ----
    ph_aggr64h(g_F2, nullptr, g_B2, g_F1, -1.f, 0.f, n, gw, nwarps);      // X1 -> B2 + F1
    gsync(nb);
    ph_aggr64h(g_F1, g_B1, g_B3, nullptr, -2.f, -1.f, n, gw, nwarps);     // X2 -> B3
    gsync(nb);
    // ---- Layers 3+4 GEMMs: in-place U->B2 (tile-local), V->F1 ----
    ph_fused_gemm<64>(g_B1, g_B2, g_B3, W2, b2, Wt2, Wp2, bt2, bp2, g_B2, g_F1, n, sA, sB);
    gsync(nb);
    ph_edge_minh(g_B2, g_F1, g_B1, g_F2, n, gw, nwarps);     // H4 -> B1 + F2
    gsync(nb);

    // ---- Layer 5 (Cheb 64->64) ----
    ph_aggr64h(g_F2, nullptr, g_B2, g_F1, -1.f, 0.f, n, gw, nwarps);      // X1 -> B2 + F1
    gsync(nb);
    ph_aggr64h(g_F1, g_B1, g_B3, nullptr, -2.f, -1.f, n, gw, nwarps);     // X2 -> B3
    gsync(nb);
    ph_cheb_gemm(g_B1, g_B2, g_B3, W3, b3, g_B4, n, sA, sB);
    gsync(nb);

    // ---- Pool: per-graph mean (graph_ids sorted) ----
    {
        int chunk = (n + nwarps - 1) / nwarps;
        int pbeg = gw * chunk, pend = min(n, pbeg + chunk);
        if (pbeg < pend) {
            float sx = 0.f, sy = 0.f;
            int cur = gid[pbeg]; int cnt = 0;
            for (int i = pbeg; i < pend; i++) {
                int g = gid[i];
                if (g != cur) {
                    atomicAdd(&g_gsum[cur * 64 + lane * 2], sx);
                    atomicAdd(&g_gsum[cur * 64 + lane * 2 + 1], sy);
                    if (lane == 0) atomicAdd(&g_gcnt[cur], cnt);
                    sx = 0.f; sy = 0.f; cnt = 0; cur = g;
                }
                float2 v = *(const float2*)(g_B4 + (size_t)i * 64 + lane * 2);
                sx += v.x; sy += v.y; cnt++;
            }
            atomicAdd(&g_gsum[cur * 64 + lane * 2], sx);
            atomicAdd(&g_gsum[cur * 64 + lane * 2 + 1], sy);
            if (lane == 0) atomicAdd(&g_gcnt[cur], cnt);
        }
    }
    gsync(nb);

    // ---- Finalize: write output + reset g_deg for next replay ----
    for (int i = gtid; i < G * 64; i += nthreads) {
        int c = g_gcnt[i >> 6];
        out[i] = g_gsum[i] / (c > 0 ? (float)c : 1.0f);
    }
    for (int i = gtid; i < n; i += nthreads) g_deg[i] = 0;
}

// ---------------- launch ----------------
extern "C" void kernel_launch(void* const* d_in, const int* in_sizes, int n_in,
                              void* d_out, int out_size) {
    const float* feat = (const float*)d_in[0];
    const int*   src  = (const int*)d_in[1];
    const int*   dst  = (const int*)d_in[2];
    const int*   gid  = (const int*)d_in[3];
    const float* W1 = (const float*)d_in[4];  const float* b1 = (const float*)d_in[5];
    const float* W2 = (const float*)d_in[6];  const float* b2 = (const float*)d_in[7];
    const float* W3 = (const float*)d_in[8];  const float* b3 = (const float*)d_in[9];
    const float* Wt1 = (const float*)d_in[10]; const float* bt1 = (const float*)d_in[11];
    const float* Wp1 = (const float*)d_in[12]; const float* bp1 = (const float*)d_in[13];
    const float* Wt2 = (const float*)d_in[14]; const float* bt2 = (const float*)d_in[15];
    const float* Wp2 = (const float*)d_in[16]; const float* bp2 = (const float*)d_in[17];
    float* out = (float*)d_out;

    const int n = in_sizes[0] / 16;
    const int e = in_sizes[1];
    const int G = out_size / 64;

    int dev = 0;
    cudaGetDevice(&dev);
    int sms = 0;
    cudaDeviceGetAttribute(&sms, cudaDevAttrMultiProcessorCount, dev);
    if (sms <= 0) sms = 148;
    int perSM = 0;
    cudaOccupancyMaxActiveBlocksPerMultiprocessor(&perSM, mega_kernel, 256, 0);
    if (perSM <= 0) perSM = 1;
    int grid = sms * perSM;
    if (grid > MAXB) grid = MAXB;

    mega_kernel<<<grid, 256>>>(feat, src, dst, gid,
                               W1, b1, W2, b2, W3, b3,
                               Wt1, bt1, Wp1, bp1, Wt2, bt2, Wp2, bp2,
                               out, n, e, G);
}

// round 10
// speedup vs baseline: 2.2325x; 2.2325x over previous
#include <cuda_runtime.h>
#include <math.h>

#define MAXN 100000
#define MAXE 1600000
#define MAXG 128
#define MAXB 1024

// ---------------- scratch (static __device__ — zero-initialized at load) ----------------
__device__ int   g_deg[MAXN];          // zeroed by finalize of previous replay (and at load)
__device__ float g_dinv[MAXN];
__device__ int   g_rowptr[MAXN + 1];
__device__ int   g_cursor[MAXN];
__device__ int   g_col[MAXE];
__device__ float g_ew[MAXE];
__device__ int   g_bsums[MAXB];
__device__ float g_B1[(size_t)MAXN * 64];
__device__ float g_B2[(size_t)MAXN * 64];
__device__ float g_B3[(size_t)MAXN * 64];
__device__ float g_B4[(size_t)MAXN * 64];
__device__ float g_gsum[MAXG * 64];
__device__ int   g_gcnt[MAXG];
__device__ unsigned g_epoch;
__device__ unsigned g_cnt;

// ---------------- packed f32x2 helpers (FFMA2 — PTX-only on sm_103a) ----------------
__device__ __forceinline__ void ffma2(unsigned long long& acc, unsigned long long w,
                                      unsigned long long x) {
    asm("fma.rn.f32x2 %0, %1, %2, %3;" : "=l"(acc) : "l"(w), "l"(x), "l"(acc));
}
__device__ __forceinline__ unsigned long long pack2(float a, float b) {
    unsigned long long r;
    asm("mov.b64 %0, {%1, %2};" : "=l"(r) : "f"(a), "f"(b));
    return r;
}
__device__ __forceinline__ float2 unpack2(unsigned long long r) {
    float2 f;
    asm("mov.b64 {%0, %1}, %2;" : "=f"(f.x), "=f"(f.y) : "l"(r));
    return f;
}

// ---------------- grid-wide barrier ----------------
__device__ __forceinline__ void gsync(int nb) {
    __syncthreads();
    if (threadIdx.x == 0) {
        __threadfence();                       // release
        volatile unsigned* ep = &g_epoch;
        unsigned e = *ep;
        if (atomicAdd(&g_cnt, 1u) == (unsigned)(nb - 1)) {
            g_cnt = 0;
            __threadfence();
            *ep = e + 1;
        } else {
            while (*ep == e) {}
            __threadfence();                   // acquire
        }
    }
    __syncthreads();
}

// ---------------- gather phases (fp32, as R8) ----------------
__device__ void ph_aggr64(const float* __restrict__ f, const float* __restrict__ extra,
                          float* __restrict__ out, float alpha, float beta,
                          int n, int gw, int nwarps) {
    const int lane = threadIdx.x & 31;
    const int sub = lane >> 4;
    const int c = (lane & 15) * 4;
    for (int node = gw; node < n; node += nwarps) {
        const int beg = g_rowptr[node], end = g_rowptr[node + 1];
        float4 acc = make_float4(0.f, 0.f, 0.f, 0.f);
        for (int e = beg; e < end; e += 4) {
            int e0 = e + sub, e1 = e + 2 + sub;
            bool v0 = e0 < end, v1 = e1 < end;
            int   s0 = v0 ? g_col[e0] : 0;  float w0 = v0 ? g_ew[e0] : 0.f;
            int   s1 = v1 ? g_col[e1] : 0;  float w1 = v1 ? g_ew[e1] : 0.f;
            float4 x0 = *(const float4*)(f + (size_t)s0 * 64 + c);
            float4 x1 = *(const float4*)(f + (size_t)s1 * 64 + c);
            acc.x = fmaf(w0, x0.x, acc.x); acc.y = fmaf(w0, x0.y, acc.y);
            acc.z = fmaf(w0, x0.z, acc.z); acc.w = fmaf(w0, x0.w, acc.w);
            acc.x = fmaf(w1, x1.x, acc.x); acc.y = fmaf(w1, x1.y, acc.y);
            acc.z = fmaf(w1, x1.z, acc.z); acc.w = fmaf(w1, x1.w, acc.w);
        }
        acc.x += __shfl_xor_sync(0xFFFFFFFFu, acc.x, 16);
        acc.y += __shfl_xor_sync(0xFFFFFFFFu, acc.y, 16);
        acc.z += __shfl_xor_sync(0xFFFFFFFFu, acc.z, 16);
        acc.w += __shfl_xor_sync(0xFFFFFFFFu, acc.w, 16);
        if (sub == 0) {
            float s = alpha * g_dinv[node];
            float4 r = make_float4(s * acc.x, s * acc.y, s * acc.z, s * acc.w);
            if (extra) {
                float4 ex = *(const float4*)(extra + (size_t)node * 64 + c);
                r.x = fmaf(beta, ex.x, r.x); r.y = fmaf(beta, ex.y, r.y);
                r.z = fmaf(beta, ex.z, r.z); r.w = fmaf(beta, ex.w, r.w);
            }
            *(float4*)(out + (size_t)node * 64 + c) = r;
        }
    }
}

__device__ void ph_aggr16(const float* __restrict__ f, const float* __restrict__ extra,
                          float* __restrict__ out, float alpha, float beta,
                          int n, int gw, int nwarps) {
    const int lane = threadIdx.x & 31;
    const int sub = lane >> 2;
    const int c = (lane & 3) * 4;
    for (int node = gw; node < n; node += nwarps) {
        const int beg = g_rowptr[node], end = g_rowptr[node + 1];
        float4 acc = make_float4(0.f, 0.f, 0.f, 0.f);
        for (int e = beg; e < end; e += 8) {
            int ee = e + sub;
            bool v = ee < end;
            int   s = v ? g_col[ee] : 0;
            float w = v ? g_ew[ee] : 0.f;
            float4 x = *(const float4*)(f + (size_t)s * 16 + c);
            acc.x = fmaf(w, x.x, acc.x); acc.y = fmaf(w, x.y, acc.y);
            acc.z = fmaf(w, x.z, acc.z); acc.w = fmaf(w, x.w, acc.w);
        }
#pragma unroll
        for (int o = 4; o < 32; o <<= 1) {
            acc.x += __shfl_xor_sync(0xFFFFFFFFu, acc.x, o);
            acc.y += __shfl_xor_sync(0xFFFFFFFFu, acc.y, o);
            acc.z += __shfl_xor_sync(0xFFFFFFFFu, acc.z, o);
            acc.w += __shfl_xor_sync(0xFFFFFFFFu, acc.w, o);
        }
        if (lane < 4) {
            float s = alpha * g_dinv[node];
            float4 r = make_float4(s * acc.x, s * acc.y, s * acc.z, s * acc.w);
            if (extra) {
                float4 ex = *(const float4*)(extra + (size_t)node * 16 + c);
                r.x = fmaf(beta, ex.x, r.x); r.y = fmaf(beta, ex.y, r.y);
                r.z = fmaf(beta, ex.z, r.z); r.w = fmaf(beta, ex.w, r.w);
            }
            *(float4*)(out + (size_t)node * 16 + c) = r;
        }
    }
}

__device__ void ph_edge_min(const float* __restrict__ U, const float* __restrict__ V,
                            float* __restrict__ out, int n, int gw, int nwarps) {
    const int lane = threadIdx.x & 31;
    const int sub = lane >> 4;
    const int c = (lane & 15) * 4;
    const float INF = 3.4e38f;
    for (int node = gw; node < n; node += nwarps) {
        const int beg = g_rowptr[node], end = g_rowptr[node + 1];
        float4 mn = make_float4(INF, INF, INF, INF);
        for (int e = beg; e < end; e += 4) {
            int e0 = e + sub, e1 = e + 2 + sub;
            if (e0 < end) {
                int s0 = g_col[e0];
                float4 x = *(const float4*)(V + (size_t)s0 * 64 + c);
                mn.x = fminf(mn.x, x.x); mn.y = fminf(mn.y, x.y);
                mn.z = fminf(mn.z, x.z); mn.w = fminf(mn.w, x.w);
            }
            if (e1 < end) {
                int s1 = g_col[e1];
                float4 x = *(const float4*)(V + (size_t)s1 * 64 + c);
                mn.x = fminf(mn.x, x.x); mn.y = fminf(mn.y, x.y);
                mn.z = fminf(mn.z, x.z); mn.w = fminf(mn.w, x.w);
            }
        }
        mn.x = fminf(mn.x, __shfl_xor_sync(0xFFFFFFFFu, mn.x, 16));
        mn.y = fminf(mn.y, __shfl_xor_sync(0xFFFFFFFFu, mn.y, 16));
        mn.z = fminf(mn.z, __shfl_xor_sync(0xFFFFFFFFu, mn.z, 16));
        mn.w = fminf(mn.w, __shfl_xor_sync(0xFFFFFFFFu, mn.w, 16));
        if (sub == 0) {
            float4 r = make_float4(0.f, 0.f, 0.f, 0.f);
            if (end > beg) {
                float4 u = *(const float4*)(U + (size_t)node * 64 + c);
                r.x = fmaxf(u.x - mn.x, 0.f); r.y = fmaxf(u.y - mn.y, 0.f);
                r.z = fmaxf(u.z - mn.z, 0.f); r.w = fmaxf(u.w - mn.w, 0.f);
            }
            *(float4*)(out + (size_t)node * 64 + c) = r;
        }
    }
}

// ---------------- GEMM machinery (2 rows x 8 cols per thread) ----------------
// XH rows stride 67: bank(XH[r][k]) = (3r + k) % 32 — conflict-free scalar x loads.
// Weight loads: all lanes in a warp share c0 = 8*warpid — full-broadcast LDS.128.

// acc[2][4] f32x2-pairs; rows ra/rb, cols c0..c0+7
__device__ __forceinline__ void gemm_sweep(unsigned long long acc[2][4],
                                           const float (*XH)[67], const float (*Ws)[64],
                                           int D, int ra, int rb, int c0) {
#pragma unroll 8
    for (int k = 0; k < D; k++) {
        float xa = XH[ra][k];
        float xb = XH[rb][k];
        unsigned long long xxa = pack2(xa, xa);
        unsigned long long xxb = pack2(xb, xb);
        const ulonglong2 w01 = *(const ulonglong2*)&Ws[k][c0];
        const ulonglong2 w23 = *(const ulonglong2*)&Ws[k][c0 + 4];
        ffma2(acc[0][0], w01.x, xxa); ffma2(acc[0][1], w01.y, xxa);
        ffma2(acc[0][2], w23.x, xxa); ffma2(acc[0][3], w23.y, xxa);
        ffma2(acc[1][0], w01.x, xxb); ffma2(acc[1][1], w01.y, xxb);
        ffma2(acc[1][2], w23.x, xxb); ffma2(acc[1][3], w23.y, xxb);
    }
}

// Load a 64xD X tile into XH (float4 global reads, scalar smem stores)
template <int D>
__device__ __forceinline__ void load_xtile(const float* __restrict__ Xj, int node0, int n,
                                           float (*XH)[67]) {
    const int tid = threadIdx.x;
    for (int i = tid; i < 64 * (D / 4); i += 256) {
        int m = i / (D / 4), q = i % (D / 4);
        int nn = node0 + m;
        float4 v = make_float4(0.f, 0.f, 0.f, 0.f);
        if (nn < n) v = *(const float4*)&Xj[(size_t)nn * D + 4 * q];
        XH[m][4 * q + 0] = v.x; XH[m][4 * q + 1] = v.y;
        XH[m][4 * q + 2] = v.z; XH[m][4 * q + 3] = v.w;
    }
}

__device__ __forceinline__ void store_row8(float* __restrict__ dst, size_t node,
                                           int c0, const unsigned long long a[4]) {
    float2 p0 = unpack2(a[0]), p1 = unpack2(a[1]), p2 = unpack2(a[2]), p3 = unpack2(a[3]);
    *(float4*)&dst[node * 64 + c0]     = make_float4(p0.x, p0.y, p1.x, p1.y);
    *(float4*)&dst[node * 64 + c0 + 4] = make_float4(p2.x, p2.y, p3.x, p3.y);
}

// Fused: H = relu(sum_j Xj@W[j] + bias) (smem only); U = H@(Wt+Wp)+bt+bp; V = H@Wt
template <int D>
__device__ void ph_fused_gemm(const float* __restrict__ X0, const float* __restrict__ X1,
                              const float* __restrict__ X2, const float* __restrict__ W,
                              const float* __restrict__ bias,
                              const float* __restrict__ Wt, const float* __restrict__ Wp,
                              const float* __restrict__ bt, const float* __restrict__ bp,
                              float* __restrict__ U, float* __restrict__ V, int n,
                              float (*XH)[67], float (*Ws)[64]) {
    const int tid = threadIdx.x;
    const int ra = tid & 31, rb = ra + 32;
    const int c0 = (tid >> 5) * 8;
    const int ntiles = (n + 63) >> 6;
    for (int t = blockIdx.x; t < ntiles; t += gridDim.x) {
        const int node0 = t * 64;
        unsigned long long acc[2][4];
#pragma unroll
        for (int p = 0; p < 4; p++) {
            unsigned long long b0 = pack2(__ldg(&bias[c0 + 2 * p]), __ldg(&bias[c0 + 2 * p + 1]));
            acc[0][p] = b0; acc[1][p] = b0;
        }
        const float* Xsrc[3] = {X0, X1, X2};
#pragma unroll
        for (int j = 0; j < 3; j++) {
            __syncthreads();
            load_xtile<D>(Xsrc[j], node0, n, XH);
            for (int i = tid; i < D * 64; i += 256) Ws[i >> 6][i & 63] = W[j * D * 64 + i];
            __syncthreads();
            gemm_sweep(acc, (const float (*)[67])XH, (const float (*)[64])Ws, D, ra, rb, c0);
        }
        __syncthreads();
        // relu -> H tile in smem (conflict-free scalar stores: rows spread over banks)
#pragma unroll
        for (int p = 0; p < 4; p++) {
            float2 a = unpack2(acc[0][p]);
            XH[ra][c0 + 2 * p] = fmaxf(a.x, 0.f);
            XH[ra][c0 + 2 * p + 1] = fmaxf(a.y, 0.f);
            float2 b2 = unpack2(acc[1][p]);
            XH[rb][c0 + 2 * p] = fmaxf(b2.x, 0.f);
            XH[rb][c0 + 2 * p + 1] = fmaxf(b2.y, 0.f);
        }
        for (int i = tid; i < 4096; i += 256) Ws[i >> 6][i & 63] = Wt[i] + Wp[i];
        __syncthreads();
#pragma unroll
        for (int p = 0; p < 4; p++) {
            unsigned long long b0 = pack2(__ldg(&bt[c0 + 2 * p]) + __ldg(&bp[c0 + 2 * p]),
                                          __ldg(&bt[c0 + 2 * p + 1]) + __ldg(&bp[c0 + 2 * p + 1]));
            acc[0][p] = b0; acc[1][p] = b0;
        }
        gemm_sweep(acc, (const float (*)[67])XH, (const float (*)[64])Ws, 64, ra, rb, c0);
        if (node0 + ra < n) store_row8(U, (size_t)(node0 + ra), c0, acc[0]);
        if (node0 + rb < n) store_row8(U, (size_t)(node0 + rb), c0, acc[1]);
        __syncthreads();
        for (int i = tid; i < 4096; i += 256) Ws[i >> 6][i & 63] = Wt[i];
        __syncthreads();
#pragma unroll
        for (int p = 0; p < 4; p++) { acc[0][p] = 0ull; acc[1][p] = 0ull; }
        gemm_sweep(acc, (const float (*)[67])XH, (const float (*)[64])Ws, 64, ra, rb, c0);
        if (node0 + ra < n) store_row8(V, (size_t)(node0 + ra), c0, acc[0]);
        if (node0 + rb < n) store_row8(V, (size_t)(node0 + rb), c0, acc[1]);
        __syncthreads();
    }
}

// Final Cheb layer: out = relu(X0@W0 + X1@W1 + X2@W2 + bias)
__device__ void ph_cheb_gemm(const float* __restrict__ X0, const float* __restrict__ X1,
                             const float* __restrict__ X2, const float* __restrict__ W,
                             const float* __restrict__ bias, float* __restrict__ out, int n,
                             float (*XH)[67], float (*Ws)[64]) {
    const int tid = threadIdx.x;
    const int ra = tid & 31, rb = ra + 32;
    const int c0 = (tid >> 5) * 8;
    const int ntiles = (n + 63) >> 6;
    for (int t = blockIdx.x; t < ntiles; t += gridDim.x) {
        const int node0 = t * 64;
        unsigned long long acc[2][4];
#pragma unroll
        for (int p = 0; p < 4; p++) {
            unsigned long long b0 = pack2(__ldg(&bias[c0 + 2 * p]), __ldg(&bias[c0 + 2 * p + 1]));
            acc[0][p] = b0; acc[1][p] = b0;
        }
        const float* Xsrc[3] = {X0, X1, X2};
#pragma unroll
        for (int j = 0; j < 3; j++) {
            __syncthreads();
            load_xtile<64>(Xsrc[j], node0, n, XH);
            for (int i = tid; i < 4096; i += 256) Ws[i >> 6][i & 63] = W[j * 4096 + i];
            __syncthreads();
            gemm_sweep(acc, (const float (*)[67])XH, (const float (*)[64])Ws, 64, ra, rb, c0);
        }
        // relu + store
#pragma unroll
        for (int p = 0; p < 4; p++) {
            float2 a = unpack2(acc[0][p]);
            acc[0][p] = pack2(fmaxf(a.x, 0.f), fmaxf(a.y, 0.f));
            float2 b2 = unpack2(acc[1][p]);
            acc[1][p] = pack2(fmaxf(b2.x, 0.f), fmaxf(b2.y, 0.f));
        }
        if (node0 + ra < n) store_row8(out, (size_t)(node0 + ra), c0, acc[0]);
        if (node0 + rb < n) store_row8(out, (size_t)(node0 + rb), c0, acc[1]);
        __syncthreads();
    }
}

// ---------------- the single persistent kernel ----------------
__global__ void __launch_bounds__(256, 4) mega_kernel(
    const float* __restrict__ feat, const int* __restrict__ src,
    const int* __restrict__ dst, const int* __restrict__ gid,
    const float* __restrict__ W1, const float* __restrict__ b1,
    const float* __restrict__ W2, const float* __restrict__ b2,
    const float* __restrict__ W3, const float* __restrict__ b3,
    const float* __restrict__ Wt1, const float* __restrict__ bt1,
    const float* __restrict__ Wp1, const float* __restrict__ bp1,
    const float* __restrict__ Wt2, const float* __restrict__ bt2,
    const float* __restrict__ Wp2, const float* __restrict__ bp2,
    float* __restrict__ out, int n, int e, int G) {
    __shared__ __align__(16) float sXH[64][67];
    __shared__ __align__(16) float sWs[64][64];
    __shared__ int s_ws[9];
    __shared__ int s_run;

    const int nb = gridDim.x;
    const int tid = threadIdx.x;
    const int lane = tid & 31, wid = tid >> 5;
    const int gtid = blockIdx.x * 256 + tid;
    const int nthreads = nb * 256;
    const int gw = blockIdx.x * 8 + wid;
    const int nwarps = nb * 8;

    // ---- B: degree count ----
    for (int i = gtid; i < e; i += nthreads) atomicAdd(&g_deg[dst[i]], 1);
    gsync(nb);

    // ---- C1: per-block exclusive scan; zero pooling accumulators ----
    for (int i = gtid; i < G * 64; i += nthreads) g_gsum[i] = 0.f;
    for (int i = gtid; i < G; i += nthreads) g_gcnt[i] = 0;
    const int per = (n + nb - 1) / nb;
    const int rng0 = blockIdx.x * per;
    const int rng1 = min(n, rng0 + per);
    if (tid == 0) s_run = 0;
    __syncthreads();
    for (int t0 = rng0; t0 < rng1; t0 += 1024) {
        int base = t0 + tid * 4;
        int v[4]; int s = 0;
#pragma unroll
        for (int j = 0; j < 4; j++) { int i = base + j; v[j] = (i < rng1) ? g_deg[i] : 0; s += v[j]; }
        int inc = s;
#pragma unroll
        for (int o = 1; o < 32; o <<= 1) { int x = __shfl_up_sync(0xFFFFFFFFu, inc, o); if (lane >= o) inc += x; }
        if (lane == 31) s_ws[wid] = inc;
        __syncthreads();
        if (wid == 0) {
            int w = (lane < 8) ? s_ws[lane] : 0;
            int winc = w;
#pragma unroll
            for (int o = 1; o < 8; o <<= 1) { int x = __shfl_up_sync(0xFFFFFFFFu, winc, o); if (lane >= o) winc += x; }
            if (lane < 8) s_ws[lane] = winc - w;
            if (lane == 7) s_ws[8] = winc;
        }
        __syncthreads();
        int off = s_run + s_ws[wid] + (inc - s);
#pragma unroll
        for (int j = 0; j < 4; j++) { int i = base + j; if (i < rng1) { g_rowptr[i] = off; off += v[j]; } }
        __syncthreads();
        if (tid == 0) s_run += s_ws[8];
        __syncthreads();
    }
    if (tid == 0) g_bsums[blockIdx.x] = s_run;
    gsync(nb);

    // ---- C3: block 0 scans block totals ----
    if (blockIdx.x == 0) {
        int base = tid * 4;
        int v[4]; int s = 0;
#pragma unroll
        for (int j = 0; j < 4; j++) { int i = base + j; v[j] = (i < nb) ? g_bsums[i] : 0; s += v[j]; }
        int inc = s;
#pragma unroll
        for (int o = 1; o < 32; o <<= 1) { int x = __shfl_up_sync(0xFFFFFFFFu, inc, o); if (lane >= o) inc += x; }
        if (lane == 31) s_ws[wid] = inc;
        __syncthreads();
        if (wid == 0) {
            int w = (lane < 8) ? s_ws[lane] : 0;
            int winc = w;
#pragma unroll
            for (int o = 1; o < 8; o <<= 1) { int x = __shfl_up_sync(0xFFFFFFFFu, winc, o); if (lane >= o) winc += x; }
            if (lane < 8) s_ws[lane] = winc - w;
        }
        __syncthreads();
        int off = s_ws[wid] + (inc - s);
#pragma unroll
        for (int j = 0; j < 4; j++) { int i = base + j; if (i < nb) { g_bsums[i] = off; off += v[j]; } }
    }
    gsync(nb);

    // ---- C5: add block offsets; cursor; dinv; rowptr[n] ----
    {
        int off = g_bsums[blockIdx.x];
        for (int i = rng0 + tid; i < rng1; i += 256) {
            int r = g_rowptr[i] + off;
            g_rowptr[i] = r;
            g_cursor[i] = r;
            int d = g_deg[i];
            g_dinv[i] = (d > 0) ? rsqrtf((float)d) : 1.0f;
        }
        if (gtid == 0) g_rowptr[n] = e;
    }
    gsync(nb);

    // ---- D: fill CSR ----
    for (int i = gtid; i < e; i += nthreads) {
        int d = dst[i], s = src[i];
        int p = atomicAdd(&g_cursor[d], 1);
        g_col[p] = s;
        g_ew[p] = g_dinv[s];
    }
    gsync(nb);

    // ---- Layer 1 (Cheb 16->64) ----
    ph_aggr16(feat, nullptr, g_B1, -1.f, 0.f, n, gw, nwarps);
    gsync(nb);
    ph_aggr16(g_B1, feat, g_B2, -2.f, -1.f, n, gw, nwarps);
    gsync(nb);
    ph_fused_gemm<16>(feat, g_B1, g_B2, W1, b1, Wt1, Wp1, bt1, bp1, g_B3, g_B4, n, sXH, sWs);
    gsync(nb);
    ph_edge_min(g_B3, g_B4, g_B1, n, gw, nwarps);       // H2 -> B1
    gsync(nb);

    // ---- Layer 3 (Cheb 64->64) ----
    ph_aggr64(g_B1, nullptr, g_B2, -1.f, 0.f, n, gw, nwarps);
    gsync(nb);
    ph_aggr64(g_B2, g_B1, g_B3, -2.f, -1.f, n, gw, nwarps);
    gsync(nb);
    ph_fused_gemm<64>(g_B1, g_B2, g_B3, W2, b2, Wt2, Wp2, bt2, bp2, g_B2, g_B3, n, sXH, sWs);
    gsync(nb);
    ph_edge_min(g_B2, g_B3, g_B1, n, gw, nwarps);       // H4 -> B1
    gsync(nb);

    // ---- Layer 5 (Cheb 64->64) ----
    ph_aggr64(g_B1, nullptr, g_B2, -1.f, 0.f, n, gw, nwarps);
    gsync(nb);
    ph_aggr64(g_B2, g_B1, g_B3, -2.f, -1.f, n, gw, nwarps);
    gsync(nb);
    ph_cheb_gemm(g_B1, g_B2, g_B3, W3, b3, g_B4, n, sXH, sWs);
    gsync(nb);

    // ---- Pool: per-graph mean (graph_ids sorted) ----
    {
        int chunk = (n + nwarps - 1) / nwarps;
        int pbeg = gw * chunk, pend = min(n, pbeg + chunk);
        if (pbeg < pend) {
            float sx = 0.f, sy = 0.f;
            int cur = gid[pbeg]; int cnt = 0;
            for (int i = pbeg; i < pend; i++) {
                int g = gid[i];
                if (g != cur) {
                    atomicAdd(&g_gsum[cur * 64 + lane * 2], sx);
                    atomicAdd(&g_gsum[cur * 64 + lane * 2 + 1], sy);
                    if (lane == 0) atomicAdd(&g_gcnt[cur], cnt);
                    sx = 0.f; sy = 0.f; cnt = 0; cur = g;
                }
                float2 v = *(const float2*)(g_B4 + (size_t)i * 64 + lane * 2);
                sx += v.x; sy += v.y; cnt++;
            }
            atomicAdd(&g_gsum[cur * 64 + lane * 2], sx);
            atomicAdd(&g_gsum[cur * 64 + lane * 2 + 1], sy);
            if (lane == 0) atomicAdd(&g_gcnt[cur], cnt);
        }
    }
    gsync(nb);

    // ---- Finalize: write output + reset g_deg for next replay ----
    for (int i = gtid; i < G * 64; i += nthreads) {
        int c = g_gcnt[i >> 6];
        out[i] = g_gsum[i] / (c > 0 ? (float)c : 1.0f);
    }
    for (int i = gtid; i < n; i += nthreads) g_deg[i] = 0;
}

// ---------------- launch ----------------
extern "C" void kernel_launch(void* const* d_in, const int* in_sizes, int n_in,
                              void* d_out, int out_size) {
    const float* feat = (const float*)d_in[0];
    const int*   src  = (const int*)d_in[1];
    const int*   dst  = (const int*)d_in[2];
    const int*   gid  = (const int*)d_in[3];
    const float* W1 = (const float*)d_in[4];  const float* b1 = (const float*)d_in[5];
    const float* W2 = (const float*)d_in[6];  const float* b2 = (const float*)d_in[7];
    const float* W3 = (const float*)d_in[8];  const float* b3 = (const float*)d_in[9];
    const float* Wt1 = (const float*)d_in[10]; const float* bt1 = (const float*)d_in[11];
    const float* Wp1 = (const float*)d_in[12]; const float* bp1 = (const float*)d_in[13];
    const float* Wt2 = (const float*)d_in[14]; const float* bt2 = (const float*)d_in[15];
    const float* Wp2 = (const float*)d_in[16]; const float* bp2 = (const float*)d_in[17];
    float* out = (float*)d_out;

    const int n = in_sizes[0] / 16;
    const int e = in_sizes[1];
    const int G = out_size / 64;

    int dev = 0;
    cudaGetDevice(&dev);
    int sms = 0;
    cudaDeviceGetAttribute(&sms, cudaDevAttrMultiProcessorCount, dev);
    if (sms <= 0) sms = 148;
    int perSM = 0;
    cudaOccupancyMaxActiveBlocksPerMultiprocessor(&perSM, mega_kernel, 256, 0);
    if (perSM <= 0) perSM = 1;
    int grid = sms * perSM;
    if (grid > MAXB) grid = MAXB;

    mega_kernel<<<grid, 256>>>(feat, src, dst, gid,
                               W1, b1, W2, b2, W3, b3,
                               Wt1, bt1, Wp1, bp1, Wt2, bt2, Wp2, bp2,
                               out, n, e, G);
}

// round 11
// speedup vs baseline: 2.2860x; 1.0240x over previous
#include <cuda_runtime.h>
#include <cuda_fp16.h>
#include <math.h>

#define MAXN 100000
#define MAXE 1600000
#define MAXG 128
#define MAXB 1024

// ---------------- scratch (static __device__ — zero-initialized at load) ----------------
__device__ int   g_deg[MAXN];          // zeroed by finalize of previous replay (and at load)
__device__ float g_dinv[MAXN];
__device__ int   g_rowptr[MAXN + 1];
__device__ int   g_cursor[MAXN];
__device__ int   g_col[MAXE];
__device__ float g_ew[MAXE];
__device__ int   g_bsums[MAXB];
__device__ float g_B1[(size_t)MAXN * 64];
__device__ float g_B2[(size_t)MAXN * 64];
__device__ float g_B3[(size_t)MAXN * 64];
__device__ float g_B4[(size_t)MAXN * 64];
__device__ __half g_F1[(size_t)MAXN * 64];   // fp16 gather operands
__device__ __half g_F2[(size_t)MAXN * 64];
__device__ __half g_feat16[(size_t)MAXN * 16];
__device__ __half g_x116[(size_t)MAXN * 16];
__device__ float g_gsum[MAXG * 64];
__device__ int   g_gcnt[MAXG];
__device__ unsigned g_epoch;
__device__ unsigned g_cnt;

// ---------------- packed f32x2 helpers (FFMA2 — PTX-only on sm_103a) ----------------
__device__ __forceinline__ void ffma2(unsigned long long& acc, unsigned long long w,
                                      unsigned long long x) {
    asm("fma.rn.f32x2 %0, %1, %2, %3;" : "=l"(acc) : "l"(w), "l"(x), "l"(acc));
}
__device__ __forceinline__ unsigned long long pack2(float a, float b) {
    unsigned long long r;
    asm("mov.b64 %0, {%1, %2};" : "=l"(r) : "f"(a), "f"(b));
    return r;
}
__device__ __forceinline__ float2 unpack2(unsigned long long r) {
    float2 f;
    asm("mov.b64 {%0, %1}, %2;" : "=f"(f.x), "=f"(f.y) : "l"(r));
    return f;
}

// ---------------- half2 <-> float2 helpers ----------------
__device__ __forceinline__ float2 h2f(unsigned u) {
    __half2 h = *reinterpret_cast<__half2*>(&u);
    return __half22float2(h);
}
__device__ __forceinline__ unsigned f2h(float a, float b) {
    __half2 h = __floats2half2_rn(a, b);
    return *reinterpret_cast<unsigned*>(&h);
}

// ---------------- grid-wide barrier ----------------
__device__ __forceinline__ void gsync(int nb) {
    __syncthreads();
    if (threadIdx.x == 0) {
        __threadfence();                       // release
        volatile unsigned* ep = &g_epoch;
        unsigned e = *ep;
        if (atomicAdd(&g_cnt, 1u) == (unsigned)(nb - 1)) {
            g_cnt = 0;
            __threadfence();
            *ep = e + 1;
        } else {
            while (*ep == e) {}
            __threadfence();                   // acquire
        }
    }
    __syncthreads();
}

// ---------------- gather phases (fp16 operands) ----------------
// out = alpha*dinv_i*sum w_e*f16[col_e] (+beta*extra_i); optional fp16 copy of result
__device__ void ph_aggr64h(const __half* __restrict__ f16, const float* __restrict__ extra,
                           float* __restrict__ out, __half* __restrict__ out16,
                           float alpha, float beta, int n, int gw, int nwarps) {
    const int lane = threadIdx.x & 31;
    const int sub = lane >> 4;
    const int c = (lane & 15) * 4;
    for (int node = gw; node < n; node += nwarps) {
        const int beg = g_rowptr[node], end = g_rowptr[node + 1];
        float4 acc = make_float4(0.f, 0.f, 0.f, 0.f);
        for (int e = beg; e < end; e += 4) {
            int e0 = e + sub, e1 = e + 2 + sub;
            bool v0 = e0 < end, v1 = e1 < end;
            int   s0 = v0 ? g_col[e0] : 0;  float w0 = v0 ? g_ew[e0] : 0.f;
            int   s1 = v1 ? g_col[e1] : 0;  float w1 = v1 ? g_ew[e1] : 0.f;
            uint2 r0 = *(const uint2*)(f16 + (size_t)s0 * 64 + c);
            uint2 r1 = *(const uint2*)(f16 + (size_t)s1 * 64 + c);
            float2 a0 = h2f(r0.x), a1 = h2f(r0.y);
            float2 b0 = h2f(r1.x), b1 = h2f(r1.y);
            acc.x = fmaf(w0, a0.x, acc.x); acc.y = fmaf(w0, a0.y, acc.y);
            acc.z = fmaf(w0, a1.x, acc.z); acc.w = fmaf(w0, a1.y, acc.w);
            acc.x = fmaf(w1, b0.x, acc.x); acc.y = fmaf(w1, b0.y, acc.y);
            acc.z = fmaf(w1, b1.x, acc.z); acc.w = fmaf(w1, b1.y, acc.w);
        }
        acc.x += __shfl_xor_sync(0xFFFFFFFFu, acc.x, 16);
        acc.y += __shfl_xor_sync(0xFFFFFFFFu, acc.y, 16);
        acc.z += __shfl_xor_sync(0xFFFFFFFFu, acc.z, 16);
        acc.w += __shfl_xor_sync(0xFFFFFFFFu, acc.w, 16);
        if (sub == 0) {
            float s = alpha * g_dinv[node];
            float4 r = make_float4(s * acc.x, s * acc.y, s * acc.z, s * acc.w);
            if (extra) {
                float4 ex = *(const float4*)(extra + (size_t)node * 64 + c);
                r.x = fmaf(beta, ex.x, r.x); r.y = fmaf(beta, ex.y, r.y);
                r.z = fmaf(beta, ex.z, r.z); r.w = fmaf(beta, ex.w, r.w);
            }
            *(float4*)(out + (size_t)node * 64 + c) = r;
            if (out16)
                *(uint2*)(out16 + (size_t)node * 64 + c) =
                    make_uint2(f2h(r.x, r.y), f2h(r.z, r.w));
        }
    }
}

__device__ void ph_aggr16h(const __half* __restrict__ f16, const float* __restrict__ extra,
                           float* __restrict__ out, __half* __restrict__ out16,
                           float alpha, float beta, int n, int gw, int nwarps) {
    const int lane = threadIdx.x & 31;
    const int sub = lane >> 2;
    const int c = (lane & 3) * 4;
    for (int node = gw; node < n; node += nwarps) {
        const int beg = g_rowptr[node], end = g_rowptr[node + 1];
        float4 acc = make_float4(0.f, 0.f, 0.f, 0.f);
        for (int e = beg; e < end; e += 8) {
            int ee = e + sub;
            bool v = ee < end;
            int   s = v ? g_col[ee] : 0;
            float w = v ? g_ew[ee] : 0.f;
            uint2 r0 = *(const uint2*)(f16 + (size_t)s * 16 + c);
            float2 a0 = h2f(r0.x), a1 = h2f(r0.y);
            acc.x = fmaf(w, a0.x, acc.x); acc.y = fmaf(w, a0.y, acc.y);
            acc.z = fmaf(w, a1.x, acc.z); acc.w = fmaf(w, a1.y, acc.w);
        }
#pragma unroll
        for (int o = 4; o < 32; o <<= 1) {
            acc.x += __shfl_xor_sync(0xFFFFFFFFu, acc.x, o);
            acc.y += __shfl_xor_sync(0xFFFFFFFFu, acc.y, o);
            acc.z += __shfl_xor_sync(0xFFFFFFFFu, acc.z, o);
            acc.w += __shfl_xor_sync(0xFFFFFFFFu, acc.w, o);
        }
        if (lane < 4) {
            float s = alpha * g_dinv[node];
            float4 r = make_float4(s * acc.x, s * acc.y, s * acc.z, s * acc.w);
            if (extra) {
                float4 ex = *(const float4*)(extra + (size_t)node * 16 + c);
                r.x = fmaf(beta, ex.x, r.x); r.y = fmaf(beta, ex.y, r.y);
                r.z = fmaf(beta, ex.z, r.z); r.w = fmaf(beta, ex.w, r.w);
            }
            *(float4*)(out + (size_t)node * 16 + c) = r;
            if (out16)
                *(uint2*)(out16 + (size_t)node * 16 + c) =
                    make_uint2(f2h(r.x, r.y), f2h(r.z, r.w));
        }
    }
}

// out_i = relu(U_i - min_{j->i} V16_j); writes fp32 + fp16 copies
__device__ void ph_edge_minh(const float* __restrict__ U, const __half* __restrict__ V16,
                             float* __restrict__ out, __half* __restrict__ out16,
                             int n, int gw, int nwarps) {
    const int lane = threadIdx.x & 31;
    const int sub = lane >> 4;
    const int c = (lane & 15) * 4;
    const float INF = 3.4e38f;
    for (int node = gw; node < n; node += nwarps) {
        const int beg = g_rowptr[node], end = g_rowptr[node + 1];
        float4 mn = make_float4(INF, INF, INF, INF);
        for (int e = beg; e < end; e += 4) {
            int e0 = e + sub, e1 = e + 2 + sub;
            if (e0 < end) {
                int s0 = g_col[e0];
                uint2 r0 = *(const uint2*)(V16 + (size_t)s0 * 64 + c);
                float2 a0 = h2f(r0.x), a1 = h2f(r0.y);
                mn.x = fminf(mn.x, a0.x); mn.y = fminf(mn.y, a0.y);
                mn.z = fminf(mn.z, a1.x); mn.w = fminf(mn.w, a1.y);
            }
            if (e1 < end) {
                int s1 = g_col[e1];
                uint2 r1 = *(const uint2*)(V16 + (size_t)s1 * 64 + c);
                float2 b0 = h2f(r1.x), b1 = h2f(r1.y);
                mn.x = fminf(mn.x, b0.x); mn.y = fminf(mn.y, b0.y);
                mn.z = fminf(mn.z, b1.x); mn.w = fminf(mn.w, b1.y);
            }
        }
        mn.x = fminf(mn.x, __shfl_xor_sync(0xFFFFFFFFu, mn.x, 16));
        mn.y = fminf(mn.y, __shfl_xor_sync(0xFFFFFFFFu, mn.y, 16));
        mn.z = fminf(mn.z, __shfl_xor_sync(0xFFFFFFFFu, mn.z, 16));
        mn.w = fminf(mn.w, __shfl_xor_sync(0xFFFFFFFFu, mn.w, 16));
        if (sub == 0) {
            float4 r = make_float4(0.f, 0.f, 0.f, 0.f);
            if (end > beg) {
                float4 u = *(const float4*)(U + (size_t)node * 64 + c);
                r.x = fmaxf(u.x - mn.x, 0.f); r.y = fmaxf(u.y - mn.y, 0.f);
                r.z = fmaxf(u.z - mn.z, 0.f); r.w = fmaxf(u.w - mn.w, 0.f);
            }
            *(float4*)(out + (size_t)node * 64 + c) = r;
            *(uint2*)(out16 + (size_t)node * 64 + c) =
                make_uint2(f2h(r.x, r.y), f2h(r.z, r.w));
        }
    }
}

// ---------------- GEMM machinery (2 rows x 8 cols per thread, R10 mapping) ----------------
__device__ __forceinline__ void gemm_sweep(unsigned long long acc[2][4],
                                           const float (*XH)[67], const float (*Ws)[64],
                                           int D, int ra, int rb, int c0) {
#pragma unroll 8
    for (int k = 0; k < D; k++) {
        float xa = XH[ra][k];
        float xb = XH[rb][k];
        unsigned long long xxa = pack2(xa, xa);
        unsigned long long xxb = pack2(xb, xb);
        const ulonglong2 w01 = *(const ulonglong2*)&Ws[k][c0];
        const ulonglong2 w23 = *(const ulonglong2*)&Ws[k][c0 + 4];
        ffma2(acc[0][0], w01.x, xxa); ffma2(acc[0][1], w01.y, xxa);
        ffma2(acc[0][2], w23.x, xxa); ffma2(acc[0][3], w23.y, xxa);
        ffma2(acc[1][0], w01.x, xxb); ffma2(acc[1][1], w01.y, xxb);
        ffma2(acc[1][2], w23.x, xxb); ffma2(acc[1][3], w23.y, xxb);
    }
}

template <int D>
__device__ __forceinline__ void load_xtile(const float* __restrict__ Xj, int node0, int n,
                                           float (*XH)[67]) {
    const int tid = threadIdx.x;
    for (int i = tid; i < 64 * (D / 4); i += 256) {
        int m = i / (D / 4), q = i % (D / 4);
        int nn = node0 + m;
        float4 v = make_float4(0.f, 0.f, 0.f, 0.f);
        if (nn < n) v = *(const float4*)&Xj[(size_t)nn * D + 4 * q];
        XH[m][4 * q + 0] = v.x; XH[m][4 * q + 1] = v.y;
        XH[m][4 * q + 2] = v.z; XH[m][4 * q + 3] = v.w;
    }
}

__device__ __forceinline__ void store_row8(float* __restrict__ dst, size_t node,
                                           int c0, const unsigned long long a[4]) {
    float2 p0 = unpack2(a[0]), p1 = unpack2(a[1]), p2 = unpack2(a[2]), p3 = unpack2(a[3]);
    *(float4*)&dst[node * 64 + c0]     = make_float4(p0.x, p0.y, p1.x, p1.y);
    *(float4*)&dst[node * 64 + c0 + 4] = make_float4(p2.x, p2.y, p3.x, p3.y);
}

__device__ __forceinline__ void store_row8h(__half* __restrict__ dst, size_t node,
                                            int c0, const unsigned long long a[4]) {
    float2 p0 = unpack2(a[0]), p1 = unpack2(a[1]), p2 = unpack2(a[2]), p3 = unpack2(a[3]);
    *(uint4*)&dst[node * 64 + c0] =
        make_uint4(f2h(p0.x, p0.y), f2h(p1.x, p1.y), f2h(p2.x, p2.y), f2h(p3.x, p3.y));
}

// Fused: H = relu(sum_j Xj@W[j] + bias) (smem only); U = H@(Wt+Wp)+bt+bp (fp32); V16 = H@Wt (fp16)
template <int D>
__device__ void ph_fused_gemm(const float* __restrict__ X0, const float* __restrict__ X1,
                              const float* __restrict__ X2, const float* __restrict__ W,
                              const float* __restrict__ bias,
                              const float* __restrict__ Wt, const float* __restrict__ Wp,
                              const float* __restrict__ bt, const float* __restrict__ bp,
                              float* __restrict__ U, __half* __restrict__ V16, int n,
                              float (*XH)[67], float (*Ws)[64]) {
    const int tid = threadIdx.x;
    const int ra = tid & 31, rb = ra + 32;
    const int c0 = (tid >> 5) * 8;
    const int ntiles = (n + 63) >> 6;
    for (int t = blockIdx.x; t < ntiles; t += gridDim.x) {
        const int node0 = t * 64;
        unsigned long long acc[2][4];
#pragma unroll
        for (int p = 0; p < 4; p++) {
            unsigned long long b0 = pack2(__ldg(&bias[c0 + 2 * p]), __ldg(&bias[c0 + 2 * p + 1]));
            acc[0][p] = b0; acc[1][p] = b0;
        }
        const float* Xsrc[3] = {X0, X1, X2};
#pragma unroll
        for (int j = 0; j < 3; j++) {
            __syncthreads();
            load_xtile<D>(Xsrc[j], node0, n, XH);
            for (int i = tid; i < D * 64; i += 256) Ws[i >> 6][i & 63] = W[j * D * 64 + i];
            __syncthreads();
            gemm_sweep(acc, (const float (*)[67])XH, (const float (*)[64])Ws, D, ra, rb, c0);
        }
        __syncthreads();
        // relu -> H tile in smem
#pragma unroll
        for (int p = 0; p < 4; p++) {
            float2 a = unpack2(acc[0][p]);
            XH[ra][c0 + 2 * p] = fmaxf(a.x, 0.f);
            XH[ra][c0 + 2 * p + 1] = fmaxf(a.y, 0.f);
            float2 b2 = unpack2(acc[1][p]);
            XH[rb][c0 + 2 * p] = fmaxf(b2.x, 0.f);
            XH[rb][c0 + 2 * p + 1] = fmaxf(b2.y, 0.f);
        }
        for (int i = tid; i < 4096; i += 256) Ws[i >> 6][i & 63] = Wt[i] + Wp[i];
        __syncthreads();
#pragma unroll
        for (int p = 0; p < 4; p++) {
            unsigned long long b0 = pack2(__ldg(&bt[c0 + 2 * p]) + __ldg(&bp[c0 + 2 * p]),
                                          __ldg(&bt[c0 + 2 * p + 1]) + __ldg(&bp[c0 + 2 * p + 1]));
            acc[0][p] = b0; acc[1][p] = b0;
        }
        gemm_sweep(acc, (const float (*)[67])XH, (const float (*)[64])Ws, 64, ra, rb, c0);
        if (node0 + ra < n) store_row8(U, (size_t)(node0 + ra), c0, acc[0]);
        if (node0 + rb < n) store_row8(U, (size_t)(node0 + rb), c0, acc[1]);
        __syncthreads();
        for (int i = tid; i < 4096; i += 256) Ws[i >> 6][i & 63] = Wt[i];
        __syncthreads();
#pragma unroll
        for (int p = 0; p < 4; p++) { acc[0][p] = 0ull; acc[1][p] = 0ull; }
        gemm_sweep(acc, (const float (*)[67])XH, (const float (*)[64])Ws, 64, ra, rb, c0);
        if (node0 + ra < n) store_row8h(V16, (size_t)(node0 + ra), c0, acc[0]);
        if (node0 + rb < n) store_row8h(V16, (size_t)(node0 + rb), c0, acc[1]);
        __syncthreads();
    }
}

// Final Cheb layer: out = relu(X0@W0 + X1@W1 + X2@W2 + bias)
__device__ void ph_cheb_gemm(const float* __restrict__ X0, const float* __restrict__ X1,
                             const float* __restrict__ X2, const float* __restrict__ W,
                             const float* __restrict__ bias, float* __restrict__ out, int n,
                             float (*XH)[67], float (*Ws)[64]) {
    const int tid = threadIdx.x;
    const int ra = tid & 31, rb = ra + 32;
    const int c0 = (tid >> 5) * 8;
    const int ntiles = (n + 63) >> 6;
    for (int t = blockIdx.x; t < ntiles; t += gridDim.x) {
        const int node0 = t * 64;
        unsigned long long acc[2][4];
#pragma unroll
        for (int p = 0; p < 4; p++) {
            unsigned long long b0 = pack2(__ldg(&bias[c0 + 2 * p]), __ldg(&bias[c0 + 2 * p + 1]));
            acc[0][p] = b0; acc[1][p] = b0;
        }
        const float* Xsrc[3] = {X0, X1, X2};
#pragma unroll
        for (int j = 0; j < 3; j++) {
            __syncthreads();
            load_xtile<64>(Xsrc[j], node0, n, XH);
            for (int i = tid; i < 4096; i += 256) Ws[i >> 6][i & 63] = W[j * 4096 + i];
            __syncthreads();
            gemm_sweep(acc, (const float (*)[67])XH, (const float (*)[64])Ws, 64, ra, rb, c0);
        }
#pragma unroll
        for (int p = 0; p < 4; p++) {
            float2 a = unpack2(acc[0][p]);
            acc[0][p] = pack2(fmaxf(a.x, 0.f), fmaxf(a.y, 0.f));
            float2 b2 = unpack2(acc[1][p]);
            acc[1][p] = pack2(fmaxf(b2.x, 0.f), fmaxf(b2.y, 0.f));
        }
        if (node0 + ra < n) store_row8(out, (size_t)(node0 + ra), c0, acc[0]);
        if (node0 + rb < n) store_row8(out, (size_t)(node0 + rb), c0, acc[1]);
        __syncthreads();
    }
}

// ---------------- the single persistent kernel ----------------
__global__ void __launch_bounds__(256, 4) mega_kernel(
    const float* __restrict__ feat, const int* __restrict__ src,
    const int* __restrict__ dst, const int* __restrict__ gid,
    const float* __restrict__ W1, const float* __restrict__ b1,
    const float* __restrict__ W2, const float* __restrict__ b2,
    const float* __restrict__ W3, const float* __restrict__ b3,
    const float* __restrict__ Wt1, const float* __restrict__ bt1,
    const float* __restrict__ Wp1, const float* __restrict__ bp1,
    const float* __restrict__ Wt2, const float* __restrict__ bt2,
    const float* __restrict__ Wp2, const float* __restrict__ bp2,
    float* __restrict__ out, int n, int e, int G) {
    __shared__ __align__(16) float sXH[64][67];
    __shared__ __align__(16) float sWs[64][64];
    __shared__ int s_ws[9];
    __shared__ int s_run;

    const int nb = gridDim.x;
    const int tid = threadIdx.x;
    const int lane = tid & 31, wid = tid >> 5;
    const int gtid = blockIdx.x * 256 + tid;
    const int nthreads = nb * 256;
    const int gw = blockIdx.x * 8 + wid;
    const int nwarps = nb * 8;

    // ---- B: degree count + fp16 copy of input features ----
    for (int i = gtid; i < e; i += nthreads) atomicAdd(&g_deg[dst[i]], 1);
    for (int i = gtid; i < n * 16; i += nthreads) g_feat16[i] = __float2half(feat[i]);
    gsync(nb);

    // ---- C1: per-block exclusive scan; zero pooling accumulators ----
    for (int i = gtid; i < G * 64; i += nthreads) g_gsum[i] = 0.f;
    for (int i = gtid; i < G; i += nthreads) g_gcnt[i] = 0;
    const int per = (n + nb - 1) / nb;
    const int rng0 = blockIdx.x * per;
    const int rng1 = min(n, rng0 + per);
    if (tid == 0) s_run = 0;
    __syncthreads();
    for (int t0 = rng0; t0 < rng1; t0 += 1024) {
        int base = t0 + tid * 4;
        int v[4]; int s = 0;
#pragma unroll
        for (int j = 0; j < 4; j++) { int i = base + j; v[j] = (i < rng1) ? g_deg[i] : 0; s += v[j]; }
        int inc = s;
#pragma unroll
        for (int o = 1; o < 32; o <<= 1) { int x = __shfl_up_sync(0xFFFFFFFFu, inc, o); if (lane >= o) inc += x; }
        if (lane == 31) s_ws[wid] = inc;
        __syncthreads();
        if (wid == 0) {
            int w = (lane < 8) ? s_ws[lane] : 0;
            int winc = w;
#pragma unroll
            for (int o = 1; o < 8; o <<= 1) { int x = __shfl_up_sync(0xFFFFFFFFu, winc, o); if (lane >= o) winc += x; }
            if (lane < 8) s_ws[lane] = winc - w;
            if (lane == 7) s_ws[8] = winc;
        }
        __syncthreads();
        int off = s_run + s_ws[wid] + (inc - s);
#pragma unroll
        for (int j = 0; j < 4; j++) { int i = base + j; if (i < rng1) { g_rowptr[i] = off; off += v[j]; } }
        __syncthreads();
        if (tid == 0) s_run += s_ws[8];
        __syncthreads();
    }
    if (tid == 0) g_bsums[blockIdx.x] = s_run;
    gsync(nb);

    // ---- C3: block 0 scans block totals ----
    if (blockIdx.x == 0) {
        int base = tid * 4;
        int v[4]; int s = 0;
#pragma unroll
        for (int j = 0; j < 4; j++) { int i = base + j; v[j] = (i < nb) ? g_bsums[i] : 0; s += v[j]; }
        int inc = s;
#pragma unroll
        for (int o = 1; o < 32; o <<= 1) { int x = __shfl_up_sync(0xFFFFFFFFu, inc, o); if (lane >= o) inc += x; }
        if (lane == 31) s_ws[wid] = inc;
        __syncthreads();
        if (wid == 0) {
            int w = (lane < 8) ? s_ws[lane] : 0;
            int winc = w;
#pragma unroll
            for (int o = 1; o < 8; o <<= 1) { int x = __shfl_up_sync(0xFFFFFFFFu, winc, o); if (lane >= o) winc += x; }
            if (lane < 8) s_ws[lane] = winc - w;
        }
        __syncthreads();
        int off = s_ws[wid] + (inc - s);
#pragma unroll
        for (int j = 0; j < 4; j++) { int i = base + j; if (i < nb) { g_bsums[i] = off; off += v[j]; } }
    }
    gsync(nb);

    // ---- C5: add block offsets; cursor; dinv; rowptr[n] ----
    {
        int off = g_bsums[blockIdx.x];
        for (int i = rng0 + tid; i < rng1; i += 256) {
            int r = g_rowptr[i] + off;
            g_rowptr[i] = r;
            g_cursor[i] = r;
            int d = g_deg[i];
            g_dinv[i] = (d > 0) ? rsqrtf((float)d) : 1.0f;
        }
        if (gtid == 0) g_rowptr[n] = e;
    }
    gsync(nb);

    // ---- D: fill CSR ----
    for (int i = gtid; i < e; i += nthreads) {
        int d = dst[i], s = src[i];
        int p = atomicAdd(&g_cursor[d], 1);
        g_col[p] = s;
        g_ew[p] = g_dinv[s];
    }
    gsync(nb);

    // ---- Layer 1 (Cheb 16->64): X1 = -aggr(feat), X2 = -2*aggr(X1) - feat ----
    ph_aggr16h(g_feat16, nullptr, g_B1, g_x116, -1.f, 0.f, n, gw, nwarps);
    gsync(nb);
    ph_aggr16h(g_x116, feat, g_B2, nullptr, -2.f, -1.f, n, gw, nwarps);
    gsync(nb);
    ph_fused_gemm<16>(feat, g_B1, g_B2, W1, b1, Wt1, Wp1, bt1, bp1, g_B3, g_F1, n, sXH, sWs);
    gsync(nb);
    ph_edge_minh(g_B3, g_F1, g_B1, g_F2, n, gw, nwarps);     // H2 -> B1 + F2
    gsync(nb);

    // ---- Layer 3 (Cheb 64->64) ----
    ph_aggr64h(g_F2, nullptr, g_B2, g_F1, -1.f, 0.f, n, gw, nwarps);   // X1 -> B2 + F1
    gsync(nb);
    ph_aggr64h(g_F1, g_B1, g_B3, nullptr, -2.f, -1.f, n, gw, nwarps);  // X2 -> B3
    gsync(nb);
    ph_fused_gemm<64>(g_B1, g_B2, g_B3, W2, b2, Wt2, Wp2, bt2, bp2, g_B2, g_F1, n, sXH, sWs);
    gsync(nb);
    ph_edge_minh(g_B2, g_F1, g_B1, g_F2, n, gw, nwarps);     // H4 -> B1 + F2
    gsync(nb);

    // ---- Layer 5 (Cheb 64->64) ----
    ph_aggr64h(g_F2, nullptr, g_B2, g_F1, -1.f, 0.f, n, gw, nwarps);   // X1 -> B2 + F1
    gsync(nb);
    ph_aggr64h(g_F1, g_B1, g_B3, nullptr, -2.f, -1.f, n, gw, nwarps);  // X2 -> B3
    gsync(nb);
    ph_cheb_gemm(g_B1, g_B2, g_B3, W3, b3, g_B4, n, sXH, sWs);
    gsync(nb);

    // ---- Pool: per-graph mean (graph_ids sorted) ----
    {
        int chunk = (n + nwarps - 1) / nwarps;
        int pbeg = gw * chunk, pend = min(n, pbeg + chunk);
        if (pbeg < pend) {
            float sx = 0.f, sy = 0.f;
            int cur = gid[pbeg]; int cnt = 0;
            for (int i = pbeg; i < pend; i++) {
                int g = gid[i];
                if (g != cur) {
                    atomicAdd(&g_gsum[cur * 64 + lane * 2], sx);
                    atomicAdd(&g_gsum[cur * 64 + lane * 2 + 1], sy);
                    if (lane == 0) atomicAdd(&g_gcnt[cur], cnt);
                    sx = 0.f; sy = 0.f; cnt = 0; cur = g;
                }
                float2 v = *(const float2*)(g_B4 + (size_t)i * 64 + lane * 2);
                sx += v.x; sy += v.y; cnt++;
            }
            atomicAdd(&g_gsum[cur * 64 + lane * 2], sx);
            atomicAdd(&g_gsum[cur * 64 + lane * 2 + 1], sy);
            if (lane == 0) atomicAdd(&g_gcnt[cur], cnt);
        }
    }
    gsync(nb);

    // ---- Finalize: write output + reset g_deg for next replay ----
    for (int i = gtid; i < G * 64; i += nthreads) {
        int c = g_gcnt[i >> 6];
        out[i] = g_gsum[i] / (c > 0 ? (float)c : 1.0f);
    }
    for (int i = gtid; i < n; i += nthreads) g_deg[i] = 0;
}

// ---------------- launch ----------------
extern "C" void kernel_launch(void* const* d_in, const int* in_sizes, int n_in,
                              void* d_out, int out_size) {
    const float* feat = (const float*)d_in[0];
    const int*   src  = (const int*)d_in[1];
    const int*   dst  = (const int*)d_in[2];
    const int*   gid  = (const int*)d_in[3];
    const float* W1 = (const float*)d_in[4];  const float* b1 = (const float*)d_in[5];
    const float* W2 = (const float*)d_in[6];  const float* b2 = (const float*)d_in[7];
    const float* W3 = (const float*)d_in[8];  const float* b3 = (const float*)d_in[9];
    const float* Wt1 = (const float*)d_in[10]; const float* bt1 = (const float*)d_in[11];
    const float* Wp1 = (const float*)d_in[12]; const float* bp1 = (const float*)d_in[13];
    const float* Wt2 = (const float*)d_in[14]; const float* bt2 = (const float*)d_in[15];
    const float* Wp2 = (const float*)d_in[16]; const float* bp2 = (const float*)d_in[17];
    float* out = (float*)d_out;

    const int n = in_sizes[0] / 16;
    const int e = in_sizes[1];
    const int G = out_size / 64;

    int dev = 0;
    cudaGetDevice(&dev);
    int sms = 0;
    cudaDeviceGetAttribute(&sms, cudaDevAttrMultiProcessorCount, dev);
    if (sms <= 0) sms = 148;
    int perSM = 0;
    cudaOccupancyMaxActiveBlocksPerMultiprocessor(&perSM, mega_kernel, 256, 0);
    if (perSM <= 0) perSM = 1;
    int grid = sms * perSM;
    if (grid > MAXB) grid = MAXB;

    mega_kernel<<<grid, 256>>>(feat, src, dst, gid,
                               W1, b1, W2, b2, W3, b3,
                               Wt1, bt1, Wp1, bp1, Wt2, bt2, Wp2, bp2,
                               out, n, e, G);
}

// round 13
// speedup vs baseline: 2.9596x; 1.2947x over previous
#include <cuda_runtime.h>
#include <cuda_fp16.h>
#include <cstdint>
#include <math.h>

#define MAXN 100000
#define MAXE 1600000
#define MAXG 128
#define MAXB 1024
#define XS 72   // half-element stride of smem tiles (144B rows: conflict-free ldmatrix)

// ---------------- scratch (static __device__ — zero-initialized at load) ----------------
__device__ int   g_deg[MAXN];          // zeroed by finalize of previous replay (and at load)
__device__ float g_dinv[MAXN];
__device__ int   g_rowptr[MAXN + 1];
__device__ int   g_cursor[MAXN];
__device__ int   g_col[MAXE];
__device__ float g_ew[MAXE];
__device__ int   g_bsums[MAXB];
__device__ float g_B1[(size_t)MAXN * 64];
__device__ float g_B2[(size_t)MAXN * 64];
__device__ float g_B3[(size_t)MAXN * 64];
__device__ float g_B4[(size_t)MAXN * 64];
__device__ __half g_F1[(size_t)MAXN * 64];   // fp16 gather operands
__device__ __half g_F2[(size_t)MAXN * 64];
__device__ __half g_feat16[(size_t)MAXN * 16];
__device__ __half g_x116[(size_t)MAXN * 16];
__device__ float g_gsum[MAXG * 64];
__device__ int   g_gcnt[MAXG];
__device__ unsigned g_epoch;
__device__ unsigned g_cnt;

// ---------------- half2 <-> float helpers ----------------
__device__ __forceinline__ float2 h2f(unsigned u) {
    __half2 h = *reinterpret_cast<__half2*>(&u);
    return __half22float2(h);
}
__device__ __forceinline__ unsigned f2h(float a, float b) {
    __half2 h = __floats2half2_rn(a, b);
    return *reinterpret_cast<unsigned*>(&h);
}

// ---------------- tensor-core primitives ----------------
__device__ __forceinline__ uint32_t smem_u32(const void* p) {
    return (uint32_t)__cvta_generic_to_shared(p);
}
__device__ __forceinline__ void ldsm_x4(unsigned r[4], uint32_t addr) {
    asm volatile("ldmatrix.sync.aligned.m8n8.x4.shared.b16 {%0,%1,%2,%3}, [%4];"
                 : "=r"(r[0]), "=r"(r[1]), "=r"(r[2]), "=r"(r[3]) : "r"(addr));
}
__device__ __forceinline__ void ldsm_x4t(unsigned r[4], uint32_t addr) {
    asm volatile("ldmatrix.sync.aligned.m8n8.x4.trans.shared.b16 {%0,%1,%2,%3}, [%4];"
                 : "=r"(r[0]), "=r"(r[1]), "=r"(r[2]), "=r"(r[3]) : "r"(addr));
}
__device__ __forceinline__ void mma16816(float c[4], const unsigned a[4], const unsigned b[2]) {
    asm volatile("mma.sync.aligned.m16n8k16.row.col.f32.f16.f16.f32 "
                 "{%0,%1,%2,%3}, {%4,%5,%6,%7}, {%8,%9}, {%0,%1,%2,%3};"
                 : "+f"(c[0]), "+f"(c[1]), "+f"(c[2]), "+f"(c[3])
                 : "r"(a[0]), "r"(a[1]), "r"(a[2]), "r"(a[3]), "r"(b[0]), "r"(b[1]));
}

// one k-step (k..k+15) for this warp's 16x32 output block
__device__ __forceinline__ void mma_step(float (*cf)[4], const __half (*XH)[XS],
                                         const __half (*WS)[XS], int m0, int n0, int k) {
    const int l = threadIdx.x & 31;
    unsigned a[4], b0[4], b1[4];
    int arow = m0 + (l & 7) + ((l >> 3) & 1) * 8;
    int acol = k + (l >> 4) * 8;
    ldsm_x4(a, smem_u32(&XH[arow][acol]));
    int brow = k + (l & 7) + ((l >> 3) & 1) * 8;
    int bc = (l >> 4) * 8;
    ldsm_x4t(b0, smem_u32(&WS[brow][n0 + bc]));
    ldsm_x4t(b1, smem_u32(&WS[brow][n0 + 16 + bc]));
    mma16816(cf[0], a, &b0[0]);
    mma16816(cf[1], a, &b0[2]);
    mma16816(cf[2], a, &b1[0]);
    mma16816(cf[3], a, &b1[2]);
}

template <int D>
__device__ __forceinline__ void mma_sweep(float (*cf)[4], const __half (*XH)[XS],
                                          const __half (*WS)[XS], int m0, int n0) {
#pragma unroll
    for (int k = 0; k < D; k += 16) mma_step(cf, XH, WS, m0, n0, k);
}

// fp32 global -> fp16 smem tile (64 x D), zero-padded rows beyond n
template <int D>
__device__ __forceinline__ void load_xtile16(const float* __restrict__ Xj, int node0, int n,
                                             __half (*XH)[XS]) {
    const int tid = threadIdx.x;
    for (int i = tid; i < 64 * (D / 2); i += 256) {
        int m = i / (D / 2), q = i % (D / 2);
        int nn = node0 + m;
        float2 v = make_float2(0.f, 0.f);
        if (nn < n) v = *(const float2*)&Xj[(size_t)nn * D + 2 * q];
        *(half2*)&XH[m][2 * q] = __floats2half2_rn(v.x, v.y);
    }
}

template <int D>
__device__ __forceinline__ void load_wtile16(const float* __restrict__ W, __half (*WS)[XS]) {
    const int tid = threadIdx.x;
    for (int i = tid; i < D * 32; i += 256) {
        int k = i >> 5, q = i & 31;
        float2 v = *(const float2*)&W[k * 64 + 2 * q];
        *(half2*)&WS[k][2 * q] = __floats2half2_rn(v.x, v.y);
    }
}

__device__ __forceinline__ void load_wtile16_sum(const float* __restrict__ A,
                                                 const float* __restrict__ B, __half (*WS)[XS]) {
    const int tid = threadIdx.x;
    for (int i = tid; i < 64 * 32; i += 256) {
        int k = i >> 5, q = i & 31;
        float2 a = *(const float2*)&A[k * 64 + 2 * q];
        float2 b = *(const float2*)&B[k * 64 + 2 * q];
        *(half2*)&WS[k][2 * q] = __floats2half2_rn(a.x + b.x, a.y + b.y);
    }
}

// ---------------- grid-wide barrier ----------------
__device__ __forceinline__ void gsync(int nb) {
    __syncthreads();
    if (threadIdx.x == 0) {
        __threadfence();                       // release
        volatile unsigned* ep = &g_epoch;
        unsigned e = *ep;
        if (atomicAdd(&g_cnt, 1u) == (unsigned)(nb - 1)) {
            g_cnt = 0;
            __threadfence();
            *ep = e + 1;
        } else {
            while (*ep == e) {}
            __threadfence();                   // acquire
        }
    }
    __syncthreads();
}

// ---------------- gather phases (fp16 operands; unchanged from R11) ----------------
__device__ void ph_aggr64h(const __half* __restrict__ f16, const float* __restrict__ extra,
                           float* __restrict__ out, __half* __restrict__ out16,
                           float alpha, float beta, int n, int gw, int nwarps) {
    const int lane = threadIdx.x & 31;
    const int sub = lane >> 4;
    const int c = (lane & 15) * 4;
    for (int node = gw; node < n; node += nwarps) {
        const int beg = g_rowptr[node], end = g_rowptr[node + 1];
        float4 acc = make_float4(0.f, 0.f, 0.f, 0.f);
        for (int e = beg; e < end; e += 4) {
            int e0 = e + sub, e1 = e + 2 + sub;
            bool v0 = e0 < end, v1 = e1 < end;
            int   s0 = v0 ? g_col[e0] : 0;  float w0 = v0 ? g_ew[e0] : 0.f;
            int   s1 = v1 ? g_col[e1] : 0;  float w1 = v1 ? g_ew[e1] : 0.f;
            uint2 r0 = *(const uint2*)(f16 + (size_t)s0 * 64 + c);
            uint2 r1 = *(const uint2*)(f16 + (size_t)s1 * 64 + c);
            float2 a0 = h2f(r0.x), a1 = h2f(r0.y);
            float2 b0 = h2f(r1.x), b1 = h2f(r1.y);
            acc.x = fmaf(w0, a0.x, acc.x); acc.y = fmaf(w0, a0.y, acc.y);
            acc.z = fmaf(w0, a1.x, acc.z); acc.w = fmaf(w0, a1.y, acc.w);
            acc.x = fmaf(w1, b0.x, acc.x); acc.y = fmaf(w1, b0.y, acc.y);
            acc.z = fmaf(w1, b1.x, acc.z); acc.w = fmaf(w1, b1.y, acc.w);
        }
        acc.x += __shfl_xor_sync(0xFFFFFFFFu, acc.x, 16);
        acc.y += __shfl_xor_sync(0xFFFFFFFFu, acc.y, 16);
        acc.z += __shfl_xor_sync(0xFFFFFFFFu, acc.z, 16);
        acc.w += __shfl_xor_sync(0xFFFFFFFFu, acc.w, 16);
        if (sub == 0) {
            float s = alpha * g_dinv[node];
            float4 r = make_float4(s * acc.x, s * acc.y, s * acc.z, s * acc.w);
            if (extra) {
                float4 ex = *(const float4*)(extra + (size_t)node * 64 + c);
                r.x = fmaf(beta, ex.x, r.x); r.y = fmaf(beta, ex.y, r.y);
                r.z = fmaf(beta, ex.z, r.z); r.w = fmaf(beta, ex.w, r.w);
            }
            *(float4*)(out + (size_t)node * 64 + c) = r;
            if (out16)
                *(uint2*)(out16 + (size_t)node * 64 + c) =
                    make_uint2(f2h(r.x, r.y), f2h(r.z, r.w));
        }
    }
}

__device__ void ph_aggr16h(const __half* __restrict__ f16, const float* __restrict__ extra,
                           float* __restrict__ out, __half* __restrict__ out16,
                           float alpha, float beta, int n, int gw, int nwarps) {
    const int lane = threadIdx.x & 31;
    const int sub = lane >> 2;
    const int c = (lane & 3) * 4;
    for (int node = gw; node < n; node += nwarps) {
        const int beg = g_rowptr[node], end = g_rowptr[node + 1];
        float4 acc = make_float4(0.f, 0.f, 0.f, 0.f);
        for (int e = beg; e < end; e += 8) {
            int ee = e + sub;
            bool v = ee < end;
            int   s = v ? g_col[ee] : 0;
            float w = v ? g_ew[ee] : 0.f;
            uint2 r0 = *(const uint2*)(f16 + (size_t)s * 16 + c);
            float2 a0 = h2f(r0.x), a1 = h2f(r0.y);
            acc.x = fmaf(w, a0.x, acc.x); acc.y = fmaf(w, a0.y, acc.y);
            acc.z = fmaf(w, a1.x, acc.z); acc.w = fmaf(w, a1.y, acc.w);
        }
#pragma unroll
        for (int o = 4; o < 32; o <<= 1) {
            acc.x += __shfl_xor_sync(0xFFFFFFFFu, acc.x, o);
            acc.y += __shfl_xor_sync(0xFFFFFFFFu, acc.y, o);
            acc.z += __shfl_xor_sync(0xFFFFFFFFu, acc.z, o);
            acc.w += __shfl_xor_sync(0xFFFFFFFFu, acc.w, o);
        }
        if (lane < 4) {
            float s = alpha * g_dinv[node];
            float4 r = make_float4(s * acc.x, s * acc.y, s * acc.z, s * acc.w);
            if (extra) {
                float4 ex = *(const float4*)(extra + (size_t)node * 16 + c);
                r.x = fmaf(beta, ex.x, r.x); r.y = fmaf(beta, ex.y, r.y);
                r.z = fmaf(beta, ex.z, r.z); r.w = fmaf(beta, ex.w, r.w);
            }
            *(float4*)(out + (size_t)node * 16 + c) = r;
            if (out16)
                *(uint2*)(out16 + (size_t)node * 16 + c) =
                    make_uint2(f2h(r.x, r.y), f2h(r.z, r.w));
        }
    }
}

__device__ void ph_edge_minh(const float* __restrict__ U, const __half* __restrict__ V16,
                             float* __restrict__ out, __half* __restrict__ out16,
                             int n, int gw, int nwarps) {
    const int lane = threadIdx.x & 31;
    const int sub = lane >> 4;
    const int c = (lane & 15) * 4;
    const float INF = 3.4e38f;
    for (int node = gw; node < n; node += nwarps) {
        const int beg = g_rowptr[node], end = g_rowptr[node + 1];
        float4 mn = make_float4(INF, INF, INF, INF);
        for (int e = beg; e < end; e += 4) {
            int e0 = e + sub, e1 = e + 2 + sub;
            if (e0 < end) {
                int s0 = g_col[e0];
                uint2 r0 = *(const uint2*)(V16 + (size_t)s0 * 64 + c);
                float2 a0 = h2f(r0.x), a1 = h2f(r0.y);
                mn.x = fminf(mn.x, a0.x); mn.y = fminf(mn.y, a0.y);
                mn.z = fminf(mn.z, a1.x); mn.w = fminf(mn.w, a1.y);
            }
            if (e1 < end) {
                int s1 = g_col[e1];
                uint2 r1 = *(const uint2*)(V16 + (size_t)s1 * 64 + c);
                float2 b0 = h2f(r1.x), b1 = h2f(r1.y);
                mn.x = fminf(mn.x, b0.x); mn.y = fminf(mn.y, b0.y);
                mn.z = fminf(mn.z, b1.x); mn.w = fminf(mn.w, b1.y);
            }
        }
        mn.x = fminf(mn.x, __shfl_xor_sync(0xFFFFFFFFu, mn.x, 16));
        mn.y = fminf(mn.y, __shfl_xor_sync(0xFFFFFFFFu, mn.y, 16));
        mn.z = fminf(mn.z, __shfl_xor_sync(0xFFFFFFFFu, mn.z, 16));
        mn.w = fminf(mn.w, __shfl_xor_sync(0xFFFFFFFFu, mn.w, 16));
        if (sub == 0) {
            float4 r = make_float4(0.f, 0.f, 0.f, 0.f);
            if (end > beg) {
                float4 u = *(const float4*)(U + (size_t)node * 64 + c);
                r.x = fmaxf(u.x - mn.x, 0.f); r.y = fmaxf(u.y - mn.y, 0.f);
                r.z = fmaxf(u.z - mn.z, 0.f); r.w = fmaxf(u.w - mn.w, 0.f);
            }
            *(float4*)(out + (size_t)node * 64 + c) = r;
            *(uint2*)(out16 + (size_t)node * 64 + c) =
                make_uint2(f2h(r.x, r.y), f2h(r.z, r.w));
        }
    }
}

// ---------------- GEMM phases (tensor-core mma) ----------------
// Fused: H = relu(sum_j Xj@W[j] + bias) (fp16, smem only); U = H@(Wt+Wp)+bt+bp; V16 = H@Wt
template <int D>
__device__ void ph_fused_gemm(const float* __restrict__ X0, const float* __restrict__ X1,
                              const float* __restrict__ X2, const float* __restrict__ W,
                              const float* __restrict__ bias,
                              const float* __restrict__ Wt, const float* __restrict__ Wp,
                              const float* __restrict__ bt, const float* __restrict__ bp,
                              float* __restrict__ U, __half* __restrict__ V16, int n,
                              __half (*XH)[XS], __half (*WS)[XS]) {
    const int tid = threadIdx.x, l = tid & 31, w = tid >> 5;
    const int m0 = (w & 3) * 16, n0 = (w >> 2) * 32;
    const int r1 = m0 + (l >> 2), r2 = r1 + 8;
    const int ntiles = (n + 63) >> 6;
    for (int t = blockIdx.x; t < ntiles; t += gridDim.x) {
        const int node0 = t * 64;
        float cf[4][4];
#pragma unroll
        for (int j4 = 0; j4 < 4; j4++) {
            int c = n0 + 8 * j4 + (l & 3) * 2;
            float b0 = __ldg(&bias[c]), b1 = __ldg(&bias[c + 1]);
            cf[j4][0] = b0; cf[j4][1] = b1; cf[j4][2] = b0; cf[j4][3] = b1;
        }
        const float* Xsrc[3] = {X0, X1, X2};
#pragma unroll
        for (int j = 0; j < 3; j++) {
            __syncthreads();
            load_xtile16<D>(Xsrc[j], node0, n, XH);
            load_wtile16<D>(W + j * D * 64, WS);
            __syncthreads();
            mma_sweep<D>(cf, (const __half (*)[XS])XH, (const __half (*)[XS])WS, m0, n0);
        }
        __syncthreads();
        // relu -> H (fp16) in XH; load Wt+Wp
#pragma unroll
        for (int j4 = 0; j4 < 4; j4++) {
            int c = n0 + 8 * j4 + (l & 3) * 2;
            *(half2*)&XH[r1][c] = __floats2half2_rn(fmaxf(cf[j4][0], 0.f), fmaxf(cf[j4][1], 0.f));
            *(half2*)&XH[r2][c] = __floats2half2_rn(fmaxf(cf[j4][2], 0.f), fmaxf(cf[j4][3], 0.f));
        }
        load_wtile16_sum(Wt, Wp, WS);
        __syncthreads();
#pragma unroll
        for (int j4 = 0; j4 < 4; j4++) {
            int c = n0 + 8 * j4 + (l & 3) * 2;
            float b0 = __ldg(&bt[c]) + __ldg(&bp[c]);
            float b1 = __ldg(&bt[c + 1]) + __ldg(&bp[c + 1]);
            cf[j4][0] = b0; cf[j4][1] = b1; cf[j4][2] = b0; cf[j4][3] = b1;
        }
        mma_sweep<64>(cf, (const __half (*)[XS])XH, (const __half (*)[XS])WS, m0, n0);
#pragma unroll
        for (int j4 = 0; j4 < 4; j4++) {
            int c = n0 + 8 * j4 + (l & 3) * 2;
            if (node0 + r1 < n)
                *(float2*)&U[(size_t)(node0 + r1) * 64 + c] = make_float2(cf[j4][0], cf[j4][1]);
            if (node0 + r2 < n)
                *(float2*)&U[(size_t)(node0 + r2) * 64 + c] = make_float2(cf[j4][2], cf[j4][3]);
        }
        __syncthreads();
        load_wtile16<64>(Wt, WS);
        __syncthreads();
#pragma unroll
        for (int j4 = 0; j4 < 4; j4++) {
            cf[j4][0] = 0.f; cf[j4][1] = 0.f; cf[j4][2] = 0.f; cf[j4][3] = 0.f;
        }
        mma_sweep<64>(cf, (const __half (*)[XS])XH, (const __half (*)[XS])WS, m0, n0);
#pragma unroll
        for (int j4 = 0; j4 < 4; j4++) {
            int c = n0 + 8 * j4 + (l & 3) * 2;
            if (node0 + r1 < n)
                *(half2*)&V16[(size_t)(node0 + r1) * 64 + c] = __floats2half2_rn(cf[j4][0], cf[j4][1]);
            if (node0 + r2 < n)
                *(half2*)&V16[(size_t)(node0 + r2) * 64 + c] = __floats2half2_rn(cf[j4][2], cf[j4][3]);
        }
        __syncthreads();
    }
}

// Final Cheb layer: out = relu(X0@W0 + X1@W1 + X2@W2 + bias), fp32 out
__device__ void ph_cheb_gemm(const float* __restrict__ X0, const float* __restrict__ X1,
                             const float* __restrict__ X2, const float* __restrict__ W,
                             const float* __restrict__ bias, float* __restrict__ out, int n,
                             __half (*XH)[XS], __half (*WS)[XS]) {
    const int tid = threadIdx.x, l = tid & 31, w = tid >> 5;
    const int m0 = (w & 3) * 16, n0 = (w >> 2) * 32;
    const int r1 = m0 + (l >> 2), r2 = r1 + 8;
    const int ntiles = (n + 63) >> 6;
    for (int t = blockIdx.x; t < ntiles; t += gridDim.x) {
        const int node0 = t * 64;
        float cf[4][4];
#pragma unroll
        for (int j4 = 0; j4 < 4; j4++) {
            int c = n0 + 8 * j4 + (l & 3) * 2;
            float b0 = __ldg(&bias[c]), b1 = __ldg(&bias[c + 1]);
            cf[j4][0] = b0; cf[j4][1] = b1; cf[j4][2] = b0; cf[j4][3] = b1;
        }
        const float* Xsrc[3] = {X0, X1, X2};
#pragma unroll
        for (int j = 0; j < 3; j++) {
            __syncthreads();
            load_xtile16<64>(Xsrc[j], node0, n, XH);
            load_wtile16<64>(W + j * 4096, WS);
            __syncthreads();
            mma_sweep<64>(cf, (const __half (*)[XS])XH, (const __half (*)[XS])WS, m0, n0);
        }
#pragma unroll
        for (int j4 = 0; j4 < 4; j4++) {
            int c = n0 + 8 * j4 + (l & 3) * 2;
            if (node0 + r1 < n)
                *(float2*)&out[(size_t)(node0 + r1) * 64 + c] =
                    make_float2(fmaxf(cf[j4][0], 0.f), fmaxf(cf[j4][1], 0.f));
            if (node0 + r2 < n)
                *(float2*)&out[(size_t)(node0 + r2) * 64 + c] =
                    make_float2(fmaxf(cf[j4][2], 0.f), fmaxf(cf[j4][3], 0.f));
        }
        __syncthreads();
    }
}

// ---------------- the single persistent kernel ----------------
__global__ void __launch_bounds__(256, 4) mega_kernel(
    const float* __restrict__ feat, const int* __restrict__ src,
    const int* __restrict__ dst, const int* __restrict__ gid,
    const float* __restrict__ W1, const float* __restrict__ b1,
    const float* __restrict__ W2, const float* __restrict__ b2,
    const float* __restrict__ W3, const float* __restrict__ b3,
    const float* __restrict__ Wt1, const float* __restrict__ bt1,
    const float* __restrict__ Wp1, const float* __restrict__ bp1,
    const float* __restrict__ Wt2, const float* __restrict__ bt2,
    const float* __restrict__ Wp2, const float* __restrict__ bp2,
    float* __restrict__ out, int n, int e, int G) {
    __shared__ __align__(16) __half sX16[64][XS];
    __shared__ __align__(16) __half sW16[64][XS];
    __shared__ int s_ws[9];
    __shared__ int s_run;

    const int nb = gridDim.x;
    const int tid = threadIdx.x;
    const int lane = tid & 31, wid = tid >> 5;
    const int gtid = blockIdx.x * 256 + tid;
    const int nthreads = nb * 256;
    const int gw = blockIdx.x * 8 + wid;
    const int nwarps = nb * 8;

    // ---- B: degree count + fp16 copy of input features ----
    for (int i = gtid; i < e; i += nthreads) atomicAdd(&g_deg[dst[i]], 1);
    for (int i = gtid; i < n * 16; i += nthreads) g_feat16[i] = __float2half(feat[i]);
    gsync(nb);

    // ---- C1: per-block exclusive scan; zero pooling accumulators ----
    for (int i = gtid; i < G * 64; i += nthreads) g_gsum[i] = 0.f;
    for (int i = gtid; i < G; i += nthreads) g_gcnt[i] = 0;
    const int per = (n + nb - 1) / nb;
    const int rng0 = blockIdx.x * per;
    const int rng1 = min(n, rng0 + per);
    if (tid == 0) s_run = 0;
    __syncthreads();
    for (int t0 = rng0; t0 < rng1; t0 += 1024) {
        int base = t0 + tid * 4;
        int v[4]; int s = 0;
#pragma unroll
        for (int j = 0; j < 4; j++) { int i = base + j; v[j] = (i < rng1) ? g_deg[i] : 0; s += v[j]; }
        int inc = s;
#pragma unroll
        for (int o = 1; o < 32; o <<= 1) { int x = __shfl_up_sync(0xFFFFFFFFu, inc, o); if (lane >= o) inc += x; }
        if (lane == 31) s_ws[wid] = inc;
        __syncthreads();
        if (wid == 0) {
            int w = (lane < 8) ? s_ws[lane] : 0;
            int winc = w;
#pragma unroll
            for (int o = 1; o < 8; o <<= 1) { int x = __shfl_up_sync(0xFFFFFFFFu, winc, o); if (lane >= o) winc += x; }
            if (lane < 8) s_ws[lane] = winc - w;
            if (lane == 7) s_ws[8] = winc;
        }
        __syncthreads();
        int off = s_run + s_ws[wid] + (inc - s);
#pragma unroll
        for (int j = 0; j < 4; j++) { int i = base + j; if (i < rng1) { g_rowptr[i] = off; off += v[j]; } }
        __syncthreads();
        if (tid == 0) s_run += s_ws[8];
        __syncthreads();
    }
    if (tid == 0) g_bsums[blockIdx.x] = s_run;
    gsync(nb);

    // ---- C3: block 0 scans block totals ----
    if (blockIdx.x == 0) {
        int base = tid * 4;
        int v[4]; int s = 0;
#pragma unroll
        for (int j = 0; j < 4; j++) { int i = base + j; v[j] = (i < nb) ? g_bsums[i] : 0; s += v[j]; }
        int inc = s;
#pragma unroll
        for (int o = 1; o < 32; o <<= 1) { int x = __shfl_up_sync(0xFFFFFFFFu, inc, o); if (lane >= o) inc += x; }
        if (lane == 31) s_ws[wid] = inc;
        __syncthreads();
        if (wid == 0) {
            int w = (lane < 8) ? s_ws[lane] : 0;
            int winc = w;
#pragma unroll
            for (int o = 1; o < 8; o <<= 1) { int x = __shfl_up_sync(0xFFFFFFFFu, winc, o); if (lane >= o) winc += x; }
            if (lane < 8) s_ws[lane] = winc - w;
        }
        __syncthreads();
        int off = s_ws[wid] + (inc - s);
#pragma unroll
        for (int j = 0; j < 4; j++) { int i = base + j; if (i < nb) { g_bsums[i] = off; off += v[j]; } }
    }
    gsync(nb);

    // ---- C5: add block offsets; cursor; dinv; rowptr[n] ----
    {
        int off = g_bsums[blockIdx.x];
        for (int i = rng0 + tid; i < rng1; i += 256) {
            int r = g_rowptr[i] + off;
            g_rowptr[i] = r;
            g_cursor[i] = r;
            int d = g_deg[i];
            g_dinv[i] = (d > 0) ? rsqrtf((float)d) : 1.0f;
        }
        if (gtid == 0) g_rowptr[n] = e;
    }
    gsync(nb);

    // ---- D: fill CSR ----
    for (int i = gtid; i < e; i += nthreads) {
        int d = dst[i], s = src[i];
        int p = atomicAdd(&g_cursor[d], 1);
        g_col[p] = s;
        g_ew[p] = g_dinv[s];
    }
    gsync(nb);

    // ---- Layer 1 (Cheb 16->64): X1 = -aggr(feat), X2 = -2*aggr(X1) - feat ----
    ph_aggr16h(g_feat16, nullptr, g_B1, g_x116, -1.f, 0.f, n, gw, nwarps);
    gsync(nb);
    ph_aggr16h(g_x116, feat, g_B2, nullptr, -2.f, -1.f, n, gw, nwarps);
    gsync(nb);
    ph_fused_gemm<16>(feat, g_B1, g_B2, W1, b1, Wt1, Wp1, bt1, bp1, g_B3, g_F1, n, sX16, sW16);
    gsync(nb);
    ph_edge_minh(g_B3, g_F1, g_B1, g_F2, n, gw, nwarps);     // H2 -> B1 + F2
    gsync(nb);

    // ---- Layer 3 (Cheb 64->64) ----
    ph_aggr64h(g_F2, nullptr, g_B2, g_F1, -1.f, 0.f, n, gw, nwarps);   // X1 -> B2 + F1
    gsync(nb);
    ph_aggr64h(g_F1, g_B1, g_B3, nullptr, -2.f, -1.f, n, gw, nwarps);  // X2 -> B3
    gsync(nb);
    ph_fused_gemm<64>(g_B1, g_B2, g_B3, W2, b2, Wt2, Wp2, bt2, bp2, g_B2, g_F1, n, sX16, sW16);
    gsync(nb);
    ph_edge_minh(g_B2, g_F1, g_B1, g_F2, n, gw, nwarps);     // H4 -> B1 + F2
    gsync(nb);

    // ---- Layer 5 (Cheb 64->64) ----
    ph_aggr64h(g_F2, nullptr, g_B2, g_F1, -1.f, 0.f, n, gw, nwarps);   // X1 -> B2 + F1
    gsync(nb);
    ph_aggr64h(g_F1, g_B1, g_B3, nullptr, -2.f, -1.f, n, gw, nwarps);  // X2 -> B3
    gsync(nb);
    ph_cheb_gemm(g_B1, g_B2, g_B3, W3, b3, g_B4, n, sX16, sW16);
    gsync(nb);

    // ---- Pool: per-graph mean (graph_ids sorted) ----
    {
        int chunk = (n + nwarps - 1) / nwarps;
        int pbeg = gw * chunk, pend = min(n, pbeg + chunk);
        if (pbeg < pend) {
            float sx = 0.f, sy = 0.f;
            int cur = gid[pbeg]; int cnt = 0;
            for (int i = pbeg; i < pend; i++) {
                int g = gid[i];
                if (g != cur) {
                    atomicAdd(&g_gsum[cur * 64 + lane * 2], sx);
                    atomicAdd(&g_gsum[cur * 64 + lane * 2 + 1], sy);
                    if (lane == 0) atomicAdd(&g_gcnt[cur], cnt);
                    sx = 0.f; sy = 0.f; cnt = 0; cur = g;
                }
                float2 v = *(const float2*)(g_B4 + (size_t)i * 64 + lane * 2);
                sx += v.x; sy += v.y; cnt++;
            }
            atomicAdd(&g_gsum[cur * 64 + lane * 2], sx);
            atomicAdd(&g_gsum[cur * 64 + lane * 2 + 1], sy);
            if (lane == 0) atomicAdd(&g_gcnt[cur], cnt);
        }
    }
    gsync(nb);

    // ---- Finalize: write output + reset g_deg for next replay ----
    for (int i = gtid; i < G * 64; i += nthreads) {
        int c = g_gcnt[i >> 6];
        out[i] = g_gsum[i] / (c > 0 ? (float)c : 1.0f);
    }
    for (int i = gtid; i < n; i += nthreads) g_deg[i] = 0;
}

// ---------------- launch ----------------
extern "C" void kernel_launch(void* const* d_in, const int* in_sizes, int n_in,
                              void* d_out, int out_size) {
    const float* feat = (const float*)d_in[0];
    const int*   src  = (const int*)d_in[1];
    const int*   dst  = (const int*)d_in[2];
    const int*   gid  = (const int*)d_in[3];
    const float* W1 = (const float*)d_in[4];  const float* b1 = (const float*)d_in[5];
    const float* W2 = (const float*)d_in[6];  const float* b2 = (const float*)d_in[7];
    const float* W3 = (const float*)d_in[8];  const float* b3 = (const float*)d_in[9];
    const float* Wt1 = (const float*)d_in[10]; const float* bt1 = (const float*)d_in[11];
    const float* Wp1 = (const float*)d_in[12]; const float* bp1 = (const float*)d_in[13];
    const float* Wt2 = (const float*)d_in[14]; const float* bt2 = (const float*)d_in[15];
    const float* Wp2 = (const float*)d_in[16]; const float* bp2 = (const float*)d_in[17];
    float* out = (float*)d_out;

    const int n = in_sizes[0] / 16;
    const int e = in_sizes[1];
    const int G = out_size / 64;

    int dev = 0;
    cudaGetDevice(&dev);
    int sms = 0;
    cudaDeviceGetAttribute(&sms, cudaDevAttrMultiProcessorCount, dev);
    if (sms <= 0) sms = 148;
    int perSM = 0;
    cudaOccupancyMaxActiveBlocksPerMultiprocessor(&perSM, mega_kernel, 256, 0);
    if (perSM <= 0) perSM = 1;
    int grid = sms * perSM;
    if (grid > MAXB) grid = MAXB;

    mega_kernel<<<grid, 256>>>(feat, src, dst, gid,
                               W1, b1, W2, b2, W3, b3,
                               Wt1, bt1, Wp1, bp1, Wt2, bt2, Wp2, bp2,
                               out, n, e, G);
}